// round 8
// baseline (speedup 1.0000x reference)
#include <cuda_runtime.h>

#define B_ 2
#define T_ 2048
#define D_ 1024
#define H_ 16
#define HD_ 64
#define NTOK (B_*T_)      // 4096
#define D3 (3*D_)         // 3072

// Scratch (static device arrays: allocation-free)
__device__ float g_q[B_*H_*T_*HD_];   // [B,H,T,HD]
__device__ float g_k[B_*H_*T_*HD_];
__device__ float g_v[B_*H_*T_*HD_];
__device__ float g_y[B_*T_*D_];       // attention output [B,T,D]

// ---------------------------------------------------------------------------
// SGEMM: C[M,N] = A[M,K] @ B[K,N] + bias[N]    (BKK=16 variant of the
// round-3 passing kernel: half the barrier frequency, same micro-tile)
// mode 1: A = x, epilogue scatters into g_q/g_k/g_v ([B,H,T,HD] layout)
// mode 2: A = g_y (ignore A arg), plain row-major write to C
// ---------------------------------------------------------------------------
#define BM 128
#define BN 128
#define BKK 16

__global__ __launch_bounds__(256)
void sgemm_kernel(const float* __restrict__ A, const float* __restrict__ Bm,
                  const float* __restrict__ bias, float* __restrict__ C,
                  int M, int N, int K, int mode)
{
    __shared__ float As[BKK][BM];
    __shared__ float Bs[BKK][BN];

    const int tid = threadIdx.x;
    const int tx = tid & 15;          // 0..15 -> col quad
    const int ty = tid >> 4;          // 0..15 -> row quad
    const int m0 = blockIdx.y * BM;
    const int n0 = blockIdx.x * BN;

    const float* __restrict__ Ap = (mode == 2) ? g_y : A;

    float acc[8][8];
#pragma unroll
    for (int i = 0; i < 8; i++)
#pragma unroll
        for (int j = 0; j < 8; j++) acc[i][j] = 0.f;

    for (int kt = 0; kt < K; kt += BKK) {
        // A: 128 rows x 4 k-quads = 512 quads; B: 16 rows x 32 col-quads = 512
        float4 va[2], vb[2];
#pragma unroll
        for (int r = 0; r < 2; r++) {
            int q = tid + r * 256;
            int arow = q >> 2, akq = (q & 3) * 4;
            va[r] = *(const float4*)&Ap[(size_t)(m0 + arow) * K + kt + akq];
            int brow = q >> 5, bc4 = (q & 31) * 4;
            vb[r] = *(const float4*)&Bm[(size_t)(kt + brow) * N + n0 + bc4];
        }

        __syncthreads();   // previous tile compute done
#pragma unroll
        for (int r = 0; r < 2; r++) {
            int q = tid + r * 256;
            int arow = q >> 2, akq = (q & 3) * 4;
            As[akq + 0][arow] = va[r].x;
            As[akq + 1][arow] = va[r].y;
            As[akq + 2][arow] = va[r].z;
            As[akq + 3][arow] = va[r].w;
            int brow = q >> 5, bc4 = (q & 31) * 4;
            *(float4*)&Bs[brow][bc4] = vb[r];
        }
        __syncthreads();

#pragma unroll
        for (int k = 0; k < BKK; k++) {
            float4 a0 = *(const float4*)&As[k][ty * 4];
            float4 a1 = *(const float4*)&As[k][ty * 4 + 64];
            float4 b0 = *(const float4*)&Bs[k][tx * 4];
            float4 b1 = *(const float4*)&Bs[k][tx * 4 + 64];
            float ar[8] = {a0.x, a0.y, a0.z, a0.w, a1.x, a1.y, a1.z, a1.w};
            float br[8] = {b0.x, b0.y, b0.z, b0.w, b1.x, b1.y, b1.z, b1.w};
#pragma unroll
            for (int i = 0; i < 8; i++)
#pragma unroll
                for (int j = 0; j < 8; j++)
                    acc[i][j] = fmaf(ar[i], br[j], acc[i][j]);
        }
    }

    // epilogue
#pragma unroll
    for (int i = 0; i < 8; i++) {
        int r = m0 + ((i < 4) ? (ty * 4 + i) : (64 + ty * 4 + i - 4));
#pragma unroll
        for (int jh = 0; jh < 2; jh++) {
            int c = n0 + jh * 64 + tx * 4;
            float4 v;
            v.x = acc[i][jh * 4 + 0] + bias[c + 0];
            v.y = acc[i][jh * 4 + 1] + bias[c + 1];
            v.z = acc[i][jh * 4 + 2] + bias[c + 2];
            v.w = acc[i][jh * 4 + 3] + bias[c + 3];
            if (mode == 1) {
                int which = c >> 10;          // c / 1024
                int rem   = c & 1023;
                int h     = rem >> 6;
                int hd    = rem & 63;
                int b     = r / T_;
                int t     = r - b * T_;
                float* dst = (which == 0) ? g_q : (which == 1) ? g_k : g_v;
                *(float4*)&dst[(((size_t)b * H_ + h) * T_ + t) * HD_ + hd] = v;
            } else {
                *(float4*)&C[(size_t)r * N + c] = v;
            }
        }
    }
}

// ---------------------------------------------------------------------------
// Causal flash attention, fp32, lane-pair split over head dim.
// Grid: (T/128, B*H). Block: 256 threads. Thread pair (2i, 2i+1) owns q-row
// q0+i; each thread of the pair owns 32 of the 64 head dims. One shfl.xor(1)
// completes each dot product. Softmax state duplicated per pair (identical).
// ~130 regs/thread -> 2 CTAs/SM -> 4 warps/SMSP (FFMA pipe fillable).
// All control flow warp-uniform: 16 consecutive rows per warp never straddle
// a 64-aligned chunk boundary; js-loop bound computed per-warp.
// ---------------------------------------------------------------------------
#define AQ 128
#define AK 64

__global__ __launch_bounds__(256, 2)
void attn_kernel()
{
    __shared__ float Ks[AK * HD_];
    __shared__ float Vs[AK * HD_];

    const int tid  = threadIdx.x;
    const int half = tid & 1;            // which 32-dim half of HD
    const int rloc = tid >> 1;           // 0..127 local q-row
    const int q0   = blockIdx.x * AQ;
    const int bh   = blockIdx.y;         // b*H + h
    const int r    = q0 + rloc;          // global q row
    const int hofs = half * 32;
    const float scl2 = 0.125f * 1.4426950408889634f;  // scale * log2(e)

    float4 q4[8];
    {
        const float4* __restrict__ qg =
            (const float4*)&g_q[((size_t)bh * T_ + r) * HD_ + hofs];
#pragma unroll
        for (int c = 0; c < 8; c++) q4[c] = qg[c];
    }
    float4 o4[8];
#pragma unroll
    for (int c = 0; c < 8; c++) o4[c] = make_float4(0.f, 0.f, 0.f, 0.f);
    float m = -1e30f, l = 0.f;

    // max local row in this warp (rows per warp: 16 consecutive)
    const int wrow_max = q0 + (tid >> 5) * 16 + 15;

    const int nchunk = q0 / AK + 2;      // keys [0, q0+128)
    for (int ck = 0; ck < nchunk; ck++) {
        const int j0 = ck * AK;
        __syncthreads();                 // prev compute done before overwrite
        {
            const float4* __restrict__ kg =
                (const float4*)&g_k[((size_t)bh * T_ + j0) * HD_];
            const float4* __restrict__ vg =
                (const float4*)&g_v[((size_t)bh * T_ + j0) * HD_];
            float4* __restrict__ ks4 = (float4*)Ks;
            float4* __restrict__ vs4 = (float4*)Vs;
            float4 kr4[4], vr4[4];
#pragma unroll
            for (int it = 0; it < 4; it++) {
                kr4[it] = kg[tid + it * 256];
                vr4[it] = vg[tid + it * 256];
            }
#pragma unroll
            for (int it = 0; it < 4; it++) {
                ks4[tid + it * 256] = kr4[it];
                vs4[tid + it * 256] = vr4[it];
            }
        }
        __syncthreads();

        if (r < j0) continue;            // warp-uniform; barrier counts match
        const int rrel   = r - j0;
        int js_end = wrow_max - j0;      // warp-uniform loop bound
        if (js_end > AK - 1) js_end = AK - 1;

#pragma unroll 1
        for (int js = 0; js <= js_end; js += 8) {
            float s[8];
#pragma unroll
            for (int jj = 0; jj < 8; jj++) {
                const float4* kr = (const float4*)&Ks[((js + jj) << 6) + hofs];
                float ax = 0.f, ay = 0.f, az = 0.f, aw = 0.f;
#pragma unroll
                for (int c = 0; c < 8; c++) {
                    float4 kv = kr[c];
                    ax = fmaf(q4[c].x, kv.x, ax);
                    ay = fmaf(q4[c].y, kv.y, ay);
                    az = fmaf(q4[c].z, kv.z, az);
                    aw = fmaf(q4[c].w, kv.w, aw);
                }
                float part = (ax + ay) + (az + aw);
                float sv = part + __shfl_xor_sync(0xffffffffu, part, 1);
                s[jj] = (js + jj > rrel) ? -1e30f : sv * scl2;
            }
            float mnew = m;
#pragma unroll
            for (int jj = 0; jj < 8; jj++) mnew = fmaxf(mnew, s[jj]);
            float corr = exp2f(m - mnew);
            m = mnew;
            l *= corr;
#pragma unroll
            for (int c = 0; c < 8; c++) {
                o4[c].x *= corr; o4[c].y *= corr;
                o4[c].z *= corr; o4[c].w *= corr;
            }
#pragma unroll
            for (int jj = 0; jj < 8; jj++) {
                float p = exp2f(s[jj] - m);
                l += p;
                const float4* vr = (const float4*)&Vs[((js + jj) << 6) + hofs];
#pragma unroll
                for (int c = 0; c < 8; c++) {
                    float4 vv = vr[c];
                    o4[c].x = fmaf(p, vv.x, o4[c].x);
                    o4[c].y = fmaf(p, vv.y, o4[c].y);
                    o4[c].z = fmaf(p, vv.z, o4[c].z);
                    o4[c].w = fmaf(p, vv.w, o4[c].w);
                }
            }
        }
    }

    // write y[b, r, h*64 + hofs + :32] = o / l   (l identical across the pair)
    const float inv = 1.0f / l;
    const int b = bh >> 4;
    const int h = bh & 15;
    float4* yout = (float4*)&g_y[((size_t)b * T_ + r) * D_ + h * HD_ + hofs];
#pragma unroll
    for (int c = 0; c < 8; c++) {
        float4 w = o4[c];
        w.x *= inv; w.y *= inv; w.z *= inv; w.w *= inv;
        yout[c] = w;
    }
}

// ---------------------------------------------------------------------------
extern "C" void kernel_launch(void* const* d_in, const int* in_sizes, int n_in,
                              void* d_out, int out_size)
{
    const float* x    = (const float*)d_in[0];
    const float* Wqkv = (const float*)d_in[1];
    const float* bqkv = (const float*)d_in[2];
    const float* Wout = (const float*)d_in[3];
    const float* bout = (const float*)d_in[4];
    float* out = (float*)d_out;

    // 1) QKV projection + bias + scatter to [B,H,T,HD]
    sgemm_kernel<<<dim3(D3 / BN, NTOK / BM), 256>>>(
        x, Wqkv, bqkv, nullptr, NTOK, D3, D_, 1);

    // 2) causal flash attention -> g_y [B,T,D]
    attn_kernel<<<dim3(T_ / AQ, B_ * H_), 256>>>();

    // 3) output projection + bias
    sgemm_kernel<<<dim3(D_ / BN, NTOK / BM), 256>>>(
        nullptr, Wout, bout, out, NTOK, D_, D_, 2);
}

// round 9
// speedup vs baseline: 1.2202x; 1.2202x over previous
#include <cuda_runtime.h>
#include <cstdint>

#define B_ 2
#define T_ 2048
#define D_ 1024
#define H_ 16
#define HD_ 64
#define NTOK (B_*T_)      // 4096
#define D3 (3*D_)         // 3072

// Scratch (static device arrays: allocation-free)
__device__ float g_q[B_*H_*T_*HD_];   // [B,H,T,HD]
__device__ float g_k[B_*H_*T_*HD_];
__device__ float g_v[B_*H_*T_*HD_];
__device__ float g_y[B_*T_*D_];       // attention output [B,T,D]

__device__ __forceinline__ uint32_t smem_u32(const void* p) {
    uint32_t a;
    asm("{ .reg .u64 t; cvta.to.shared.u64 t, %1; cvt.u32.u64 %0, t; }"
        : "=r"(a) : "l"(p));
    return a;
}

// ---------------------------------------------------------------------------
// SGEMM: C[M,N] = A[M,K] @ B[K,N] + bias[N]
// cp.async double-buffered: one barrier per K-iter, loads hidden under FMAs.
// mode 1: A = x, epilogue scatters into g_q/g_k/g_v ([B,H,T,HD] layout)
// mode 2: A = g_y (ignore A arg), plain row-major write to C
// ---------------------------------------------------------------------------
#define BM 128
#define BN 128
#define BKK 8

__global__ __launch_bounds__(256)
void sgemm_kernel(const float* __restrict__ A, const float* __restrict__ Bm,
                  const float* __restrict__ bias, float* __restrict__ C,
                  int M, int N, int K, int mode)
{
    __shared__ float As[2][BKK][BM];
    __shared__ float Bs[2][BKK][BN];

    const int tid = threadIdx.x;
    const int tx = tid & 15;          // 0..15 -> col quad
    const int ty = tid >> 4;          // 0..15 -> row quad
    const int m0 = blockIdx.y * BM;
    const int n0 = blockIdx.x * BN;

    const float* __restrict__ Ap = (mode == 2) ? g_y : A;

    // B staging: thread -> (row = tid>>5, col quad = (tid&31)*4), 16B cp.async
    const int brow = tid >> 5;
    const int bc4  = (tid & 31) * 4;

    float acc[8][8];
#pragma unroll
    for (int i = 0; i < 8; i++)
#pragma unroll
        for (int j = 0; j < 8; j++) acc[i][j] = 0.f;

    // issue one tile's cp.asyncs into buffer `buf` for k-offset kt
    auto stage = [&](int buf, int kt) {
        // A: 1024 elems, 4 per thread, 4-byte copies (transposed store)
#pragma unroll
        for (int j = 0; j < 4; j++) {
            int e = tid + j * 256;
            int row = e >> 3, k = e & 7;
            uint32_t dst = smem_u32(&As[buf][k][row]);
            const float* src = &Ap[(size_t)(m0 + row) * K + kt + k];
            asm volatile("cp.async.ca.shared.global [%0], [%1], 4;"
                         :: "r"(dst), "l"(src));
        }
        // B: 16-byte copy, layout-preserving
        {
            uint32_t dst = smem_u32(&Bs[buf][brow][bc4]);
            const float* src = &Bm[(size_t)(kt + brow) * N + n0 + bc4];
            asm volatile("cp.async.ca.shared.global [%0], [%1], 16;"
                         :: "r"(dst), "l"(src));
        }
        asm volatile("cp.async.commit_group;");
    };

    stage(0, 0);

    const int niter = K / BKK;
    for (int it = 0; it < niter; it++) {
        const int cur = it & 1;
        if (it + 1 < niter) {
            stage(cur ^ 1, (it + 1) * BKK);
            asm volatile("cp.async.wait_group 1;");
        } else {
            asm volatile("cp.async.wait_group 0;");
        }
        __syncthreads();

#pragma unroll
        for (int k = 0; k < BKK; k++) {
            float4 a0 = *(const float4*)&As[cur][k][ty * 4];
            float4 a1 = *(const float4*)&As[cur][k][ty * 4 + 64];
            float4 b0 = *(const float4*)&Bs[cur][k][tx * 4];
            float4 b1 = *(const float4*)&Bs[cur][k][tx * 4 + 64];
            float ar[8] = {a0.x, a0.y, a0.z, a0.w, a1.x, a1.y, a1.z, a1.w};
            float br[8] = {b0.x, b0.y, b0.z, b0.w, b1.x, b1.y, b1.z, b1.w};
#pragma unroll
            for (int i = 0; i < 8; i++)
#pragma unroll
                for (int j = 0; j < 8; j++)
                    acc[i][j] = fmaf(ar[i], br[j], acc[i][j]);
        }
        // no trailing barrier needed: next iter's cp.async targets the other
        // buffer, and its barrier orders buffer reuse two iters apart.
    }

    // epilogue
#pragma unroll
    for (int i = 0; i < 8; i++) {
        int r = m0 + ((i < 4) ? (ty * 4 + i) : (64 + ty * 4 + i - 4));
#pragma unroll
        for (int jh = 0; jh < 2; jh++) {
            int c = n0 + jh * 64 + tx * 4;
            float4 v;
            v.x = acc[i][jh * 4 + 0] + bias[c + 0];
            v.y = acc[i][jh * 4 + 1] + bias[c + 1];
            v.z = acc[i][jh * 4 + 2] + bias[c + 2];
            v.w = acc[i][jh * 4 + 3] + bias[c + 3];
            if (mode == 1) {
                int which = c >> 10;          // c / 1024
                int rem   = c & 1023;
                int h     = rem >> 6;
                int hd    = rem & 63;
                int b     = r / T_;
                int t     = r - b * T_;
                float* dst = (which == 0) ? g_q : (which == 1) ? g_k : g_v;
                *(float4*)&dst[(((size_t)b * H_ + h) * T_ + t) * HD_ + hd] = v;
            } else {
                *(float4*)&C[(size_t)r * N + c] = v;
            }
        }
    }
}

// ---------------------------------------------------------------------------
// Causal flash attention, fp32 — byte-identical round-3 body, except q-tiles
// are scheduled HEAVY-FIRST (reversed blockIdx.x) to fix causal imbalance:
// the longest tiles (most KV chunks) start first, so the tail is light.
// ---------------------------------------------------------------------------
#define AQ 128
#define AK 64

__global__ __launch_bounds__(128)
void attn_kernel()
{
    __shared__ float Ks[AK * HD_];
    __shared__ float Vs[AK * HD_];

    const int tid = threadIdx.x;
    const int qt  = gridDim.x - 1 - blockIdx.x;   // heavy-first
    const int q0  = qt * AQ;
    const int bh  = blockIdx.y;
    const int r   = q0 + tid;
    const float scl2 = 0.125f * 1.4426950408889634f;  // scale * log2(e)

    float4 q4[16];
    {
        const float4* __restrict__ qg =
            (const float4*)&g_q[((size_t)bh * T_ + r) * HD_];
#pragma unroll
        for (int c = 0; c < 16; c++) q4[c] = qg[c];
    }
    float4 o4[16];
#pragma unroll
    for (int c = 0; c < 16; c++) o4[c] = make_float4(0.f, 0.f, 0.f, 0.f);
    float m = -1e30f, l = 0.f;

    const int nchunk = q0 / AK + 2;
    for (int ck = 0; ck < nchunk; ck++) {
        const int j0 = ck * AK;
        __syncthreads();
        {
            const float4* __restrict__ kg =
                (const float4*)&g_k[((size_t)bh * T_ + j0) * HD_];
            const float4* __restrict__ vg =
                (const float4*)&g_v[((size_t)bh * T_ + j0) * HD_];
            float4* __restrict__ ks4 = (float4*)Ks;
            float4* __restrict__ vs4 = (float4*)Vs;
            float4 kr8[8], vr8[8];
#pragma unroll
            for (int it = 0; it < 8; it++) {
                kr8[it] = kg[tid + it * 128];
                vr8[it] = vg[tid + it * 128];
            }
#pragma unroll
            for (int it = 0; it < 8; it++) {
                ks4[tid + it * 128] = kr8[it];
                vs4[tid + it * 128] = vr8[it];
            }
        }
        __syncthreads();

        if (r < j0) continue;
        const int rrel = r - j0;

#pragma unroll 1
        for (int js = 0; js < AK; js += 16) {
            if (js > rrel) break;
            float s[16];
#pragma unroll
            for (int jj = 0; jj < 16; jj++) {
                const float4* kr = (const float4*)&Ks[(js + jj) << 6];
                float ax = 0.f, ay = 0.f, az = 0.f, aw = 0.f;
#pragma unroll
                for (int c = 0; c < 16; c++) {
                    float4 kv = kr[c];
                    ax = fmaf(q4[c].x, kv.x, ax);
                    ay = fmaf(q4[c].y, kv.y, ay);
                    az = fmaf(q4[c].z, kv.z, az);
                    aw = fmaf(q4[c].w, kv.w, aw);
                }
                float sv = (ax + ay) + (az + aw);
                s[jj] = (js + jj > rrel) ? -1e30f : sv * scl2;
            }
            float mnew = m;
#pragma unroll
            for (int jj = 0; jj < 16; jj++) mnew = fmaxf(mnew, s[jj]);
            float corr = exp2f(m - mnew);
            m = mnew;
            l *= corr;
#pragma unroll
            for (int c = 0; c < 16; c++) {
                o4[c].x *= corr; o4[c].y *= corr;
                o4[c].z *= corr; o4[c].w *= corr;
            }
#pragma unroll
            for (int jj = 0; jj < 16; jj++) {
                float p = exp2f(s[jj] - mnew);
                l += p;
                const float4* vr = (const float4*)&Vs[(js + jj) << 6];
#pragma unroll
                for (int c = 0; c < 16; c++) {
                    float4 vv = vr[c];
                    o4[c].x = fmaf(p, vv.x, o4[c].x);
                    o4[c].y = fmaf(p, vv.y, o4[c].y);
                    o4[c].z = fmaf(p, vv.z, o4[c].z);
                    o4[c].w = fmaf(p, vv.w, o4[c].w);
                }
            }
        }
    }

    const float inv = 1.0f / l;
    const int b = bh >> 4;
    const int h = bh & 15;
    float4* yout = (float4*)&g_y[((size_t)b * T_ + r) * D_ + h * HD_];
#pragma unroll
    for (int c = 0; c < 16; c++) {
        float4 w = o4[c];
        w.x *= inv; w.y *= inv; w.z *= inv; w.w *= inv;
        yout[c] = w;
    }
}

// ---------------------------------------------------------------------------
extern "C" void kernel_launch(void* const* d_in, const int* in_sizes, int n_in,
                              void* d_out, int out_size)
{
    const float* x    = (const float*)d_in[0];
    const float* Wqkv = (const float*)d_in[1];
    const float* bqkv = (const float*)d_in[2];
    const float* Wout = (const float*)d_in[3];
    const float* bout = (const float*)d_in[4];
    float* out = (float*)d_out;

    // 1) QKV projection + bias + scatter to [B,H,T,HD]
    sgemm_kernel<<<dim3(D3 / BN, NTOK / BM), 256>>>(
        x, Wqkv, bqkv, nullptr, NTOK, D3, D_, 1);

    // 2) causal flash attention -> g_y [B,T,D]
    attn_kernel<<<dim3(T_ / AQ, B_ * H_), 128>>>();

    // 3) output projection + bias
    sgemm_kernel<<<dim3(D_ / BN, NTOK / BM), 256>>>(
        nullptr, Wout, bout, out, NTOK, D_, D_, 2);
}

// round 11
// speedup vs baseline: 1.6879x; 1.3833x over previous
#include <cuda_runtime.h>
#include <cuda_bf16.h>
#include <mma.h>
#include <cstdint>

#define B_ 2
#define T_ 2048
#define D_ 1024
#define H_ 16
#define HD_ 64
#define NTOK (B_*T_)      // 4096
#define D3 (3*D_)         // 3072

using namespace nvcuda;

// ---------------------------------------------------------------------------
// Scratch (static device arrays: allocation-free).
// CRITICAL RULE (round-10 lesson): these symbols are NEVER passed as kernel
// arguments from host code — host-side references to __device__ symbols give
// garbage addresses. All access is from device code inside the kernels.
// ---------------------------------------------------------------------------
__device__ float g_q[B_*H_*T_*HD_];   // [B,H,T,HD]
__device__ float g_k[B_*H_*T_*HD_];
__device__ float g_v[B_*H_*T_*HD_];
__device__ float g_y[B_*T_*D_];       // attention output [B,T,D]

__device__ __nv_bfloat16 g_Ah[NTOK*D_];   // activation hi/lo (x, then g_y)
__device__ __nv_bfloat16 g_Al[NTOK*D_];
__device__ __nv_bfloat16 g_Wh[D3*D_];     // Wqkv^T [N=3072,K=1024] hi/lo
__device__ __nv_bfloat16 g_Wl[D3*D_];
__device__ __nv_bfloat16 g_Uh[D_*D_];     // Wout^T [N=1024,K=1024] hi/lo
__device__ __nv_bfloat16 g_Ul[D_*D_];

// ---------------------------------------------------------------------------
// bf16 split conversions. Scratch targets resolved DEVICE-SIDE via mode.
// ---------------------------------------------------------------------------
// mode 0: src = A (harness x);  mode 1: src = g_y
__global__ void conva_kernel(const float* __restrict__ A, int n4, int mode)
{
    int i = blockIdx.x * blockDim.x + threadIdx.x;
    if (i >= n4) return;
    const float* __restrict__ src = (mode == 0) ? A : g_y;
    float4 v = ((const float4*)src)[i];
    float xs[4] = {v.x, v.y, v.z, v.w};
    __nv_bfloat16 h[4], l[4];
#pragma unroll
    for (int j = 0; j < 4; j++) {
        h[j] = __float2bfloat16(xs[j]);
        l[j] = __float2bfloat16(xs[j] - __bfloat162float(h[j]));
    }
    __nv_bfloat162* Ah2 = (__nv_bfloat162*)g_Ah;
    __nv_bfloat162* Al2 = (__nv_bfloat162*)g_Al;
    Ah2[2*i+0] = __halves2bfloat162(h[0], h[1]);
    Ah2[2*i+1] = __halves2bfloat162(h[2], h[3]);
    Al2[2*i+0] = __halves2bfloat162(l[0], l[1]);
    Al2[2*i+1] = __halves2bfloat162(l[2], l[3]);
}

// W[K,N] -> (mode 0: g_Wh/g_Wl, mode 1: g_Uh/g_Ul)[N,K], transposed + split.
// block(32,8), grid(N/32, K/32)
__global__ void convw_kernel(const float* __restrict__ W, int K, int N, int mode)
{
    __shared__ float t[32][33];
    __nv_bfloat16* __restrict__ Th = (mode == 0) ? g_Wh : g_Uh;
    __nv_bfloat16* __restrict__ Tl = (mode == 0) ? g_Wl : g_Ul;
    int n0 = blockIdx.x * 32, k0 = blockIdx.y * 32;
    int tx = threadIdx.x, ty = threadIdx.y;
#pragma unroll
    for (int i = 0; i < 4; i++)
        t[ty + i*8][tx] = W[(size_t)(k0 + ty + i*8) * N + n0 + tx];
    __syncthreads();
#pragma unroll
    for (int i = 0; i < 4; i++) {
        int n = n0 + ty + i*8, k = k0 + tx;
        float x = t[tx][ty + i*8];
        __nv_bfloat16 h = __float2bfloat16(x);
        __nv_bfloat16 l = __float2bfloat16(x - __bfloat162float(h));
        Th[(size_t)n * K + k] = h;
        Tl[(size_t)n * K + k] = l;
    }
}

// ---------------------------------------------------------------------------
// WMMA GEMM: C[M,N] = split(A[M,K]) @ split(B[N,K])^T + bias
// A = g_Ah/g_Al (device-side), B = g_Wh/g_Wl (mode 1) or g_Uh/g_Ul (mode 2).
// 128x128 CTA tile, 8 warps (2x4), warp tile 64x32 (4x2 wmma 16x16x16 tiles).
// K-chunk 32, smem 4 x (128 x 40 bf16) = 40960 B (static, <48KB).
// 3 compensated passes per k-step: AhBh, AhBl, AlBh; fp32 accumulators.
// mode 1: scatter into g_q/g_k/g_v      mode 2: plain write to C
// ---------------------------------------------------------------------------
#define GKC 32
#define G_LDS 40                               // padded row stride (bf16)
#define G_TILE (128*G_LDS)                     // 5120 bf16 per tile

__global__ void __launch_bounds__(256)
mma_gemm(const float* __restrict__ bias, float* __restrict__ C,
         int N, int K, int mode)
{
    __shared__ __nv_bfloat16 sm[4 * G_TILE];   // 40960 B
    __nv_bfloat16* sAh = sm;
    __nv_bfloat16* sAl = sm + G_TILE;
    __nv_bfloat16* sBh = sm + 2*G_TILE;
    __nv_bfloat16* sBl = sm + 3*G_TILE;

    const int tid  = threadIdx.x;
    const int wid  = tid >> 5, lane = tid & 31;
    const int wM   = wid & 1,  wN = wid >> 1;     // 2 x 4 warp grid
    const int m0   = blockIdx.y * 128, n0 = blockIdx.x * 128;

    const __nv_bfloat16* __restrict__ Bh = (mode == 1) ? g_Wh : g_Uh;
    const __nv_bfloat16* __restrict__ Bl = (mode == 1) ? g_Wl : g_Ul;

    const __nv_bfloat16* pAh = g_Ah + (size_t)m0 * K;
    const __nv_bfloat16* pAl = g_Al + (size_t)m0 * K;
    const __nv_bfloat16* pBh = Bh + (size_t)n0 * K;
    const __nv_bfloat16* pBl = Bl + (size_t)n0 * K;

    wmma::fragment<wmma::accumulator, 16, 16, 16, float> acc[4][2];
#pragma unroll
    for (int mt = 0; mt < 4; mt++)
#pragma unroll
        for (int nt = 0; nt < 2; nt++) wmma::fill_fragment(acc[mt][nt], 0.0f);

    // per-chunk gmem staging: 4 arrays x 2 uint4 per thread
    uint4 rg[8];
#pragma unroll
    for (int r = 0; r < 2; r++) {
        int i = tid + r * 256, row = i >> 2, c8 = i & 3;
        size_t go = (size_t)row * K + c8 * 8;
        rg[r]     = *(const uint4*)(pAh + go);
        rg[2 + r] = *(const uint4*)(pAl + go);
        rg[4 + r] = *(const uint4*)(pBh + go);
        rg[6 + r] = *(const uint4*)(pBl + go);
    }

    const int nch = K / GKC;
    for (int ch = 0; ch < nch; ch++) {
        __syncthreads();                       // prev chunk's compute done
#pragma unroll
        for (int r = 0; r < 2; r++) {
            int i = tid + r * 256, row = i >> 2, c8 = i & 3;
            int so = row * G_LDS + c8 * 8;
            *(uint4*)(sAh + so) = rg[r];
            *(uint4*)(sAl + so) = rg[2 + r];
            *(uint4*)(sBh + so) = rg[4 + r];
            *(uint4*)(sBl + so) = rg[6 + r];
        }
        __syncthreads();

        if (ch + 1 < nch) {                    // prefetch next chunk
            int kc = (ch + 1) * GKC;
#pragma unroll
            for (int r = 0; r < 2; r++) {
                int i = tid + r * 256, row = i >> 2, c8 = i & 3;
                size_t go = (size_t)row * K + kc + c8 * 8;
                rg[r]     = *(const uint4*)(pAh + go);
                rg[2 + r] = *(const uint4*)(pAl + go);
                rg[4 + r] = *(const uint4*)(pBh + go);
                rg[6 + r] = *(const uint4*)(pBl + go);
            }
        }

#pragma unroll
        for (int ks = 0; ks < 2; ks++) {
            const int k0 = ks * 16;
            wmma::fragment<wmma::matrix_a, 16, 16, 16, __nv_bfloat16,
                           wmma::row_major> ah[4], al[4];
            wmma::fragment<wmma::matrix_b, 16, 16, 16, __nv_bfloat16,
                           wmma::col_major> bh[2], bl[2];
#pragma unroll
            for (int mt = 0; mt < 4; mt++) {
                int rb = wM * 64 + mt * 16;
                wmma::load_matrix_sync(ah[mt], sAh + rb * G_LDS + k0, G_LDS);
                wmma::load_matrix_sync(al[mt], sAl + rb * G_LDS + k0, G_LDS);
            }
#pragma unroll
            for (int nt = 0; nt < 2; nt++) {
                int nb = wN * 32 + nt * 16;
                wmma::load_matrix_sync(bh[nt], sBh + nb * G_LDS + k0, G_LDS);
                wmma::load_matrix_sync(bl[nt], sBl + nb * G_LDS + k0, G_LDS);
            }
#pragma unroll
            for (int mt = 0; mt < 4; mt++)
#pragma unroll
                for (int nt = 0; nt < 2; nt++) {
                    wmma::mma_sync(acc[mt][nt], ah[mt], bh[nt], acc[mt][nt]);
                    wmma::mma_sync(acc[mt][nt], ah[mt], bl[nt], acc[mt][nt]);
                    wmma::mma_sync(acc[mt][nt], al[mt], bh[nt], acc[mt][nt]);
                }
        }
    }

    // epilogue: reuse tile smem as per-warp 16x16 float scratch
    __syncthreads();
    float* scratch = (float*)sm + wid * 256;   // 1KB per warp, 8KB total
#pragma unroll
    for (int mt = 0; mt < 4; mt++) {
#pragma unroll
        for (int nt = 0; nt < 2; nt++) {
            wmma::store_matrix_sync(scratch, acc[mt][nt], 16, wmma::mem_row_major);
            __syncwarp();
            int row0 = m0 + wM * 64 + mt * 16;
            int col0 = n0 + wN * 32 + nt * 16;
#pragma unroll
            for (int e = lane; e < 256; e += 32) {
                int rr = e >> 4, cc = e & 15;
                int r = row0 + rr, col = col0 + cc;
                float v = scratch[e] + bias[col];
                if (mode == 1) {
                    int which = col >> 10;
                    int rem   = col & 1023;
                    int h     = rem >> 6;
                    int hd    = rem & 63;
                    int b     = r / T_;
                    int t     = r - b * T_;
                    float* dst = (which == 0) ? g_q : (which == 1) ? g_k : g_v;
                    dst[(((size_t)b * H_ + h) * T_ + t) * HD_ + hd] = v;
                } else {
                    C[(size_t)r * N + col] = v;
                }
            }
            __syncwarp();
        }
    }
}

// ---------------------------------------------------------------------------
// Causal flash attention, fp32 — byte-identical to the round-3 passing kernel.
// ---------------------------------------------------------------------------
#define AQ 128
#define AK 64

__global__ __launch_bounds__(128)
void attn_kernel()
{
    __shared__ float Ks[AK * HD_];
    __shared__ float Vs[AK * HD_];

    const int tid = threadIdx.x;
    const int q0  = blockIdx.x * AQ;
    const int bh  = blockIdx.y;
    const int r   = q0 + tid;
    const float scl2 = 0.125f * 1.4426950408889634f;  // scale * log2(e)

    float4 q4[16];
    {
        const float4* __restrict__ qg =
            (const float4*)&g_q[((size_t)bh * T_ + r) * HD_];
#pragma unroll
        for (int c = 0; c < 16; c++) q4[c] = qg[c];
    }
    float4 o4[16];
#pragma unroll
    for (int c = 0; c < 16; c++) o4[c] = make_float4(0.f, 0.f, 0.f, 0.f);
    float m = -1e30f, l = 0.f;

    const int nchunk = q0 / AK + 2;
    for (int ck = 0; ck < nchunk; ck++) {
        const int j0 = ck * AK;
        __syncthreads();
        {
            const float4* __restrict__ kg =
                (const float4*)&g_k[((size_t)bh * T_ + j0) * HD_];
            const float4* __restrict__ vg =
                (const float4*)&g_v[((size_t)bh * T_ + j0) * HD_];
            float4* __restrict__ ks4 = (float4*)Ks;
            float4* __restrict__ vs4 = (float4*)Vs;
            float4 kr8[8], vr8[8];
#pragma unroll
            for (int it = 0; it < 8; it++) {
                kr8[it] = kg[tid + it * 128];
                vr8[it] = vg[tid + it * 128];
            }
#pragma unroll
            for (int it = 0; it < 8; it++) {
                ks4[tid + it * 128] = kr8[it];
                vs4[tid + it * 128] = vr8[it];
            }
        }
        __syncthreads();

        if (r < j0) continue;
        const int rrel = r - j0;

#pragma unroll 1
        for (int js = 0; js < AK; js += 16) {
            if (js > rrel) break;
            float s[16];
#pragma unroll
            for (int jj = 0; jj < 16; jj++) {
                const float4* kr = (const float4*)&Ks[(js + jj) << 6];
                float ax = 0.f, ay = 0.f, az = 0.f, aw = 0.f;
#pragma unroll
                for (int c = 0; c < 16; c++) {
                    float4 kv = kr[c];
                    ax = fmaf(q4[c].x, kv.x, ax);
                    ay = fmaf(q4[c].y, kv.y, ay);
                    az = fmaf(q4[c].z, kv.z, az);
                    aw = fmaf(q4[c].w, kv.w, aw);
                }
                float sv = (ax + ay) + (az + aw);
                s[jj] = (js + jj > rrel) ? -1e30f : sv * scl2;
            }
            float mnew = m;
#pragma unroll
            for (int jj = 0; jj < 16; jj++) mnew = fmaxf(mnew, s[jj]);
            float corr = exp2f(m - mnew);
            m = mnew;
            l *= corr;
#pragma unroll
            for (int c = 0; c < 16; c++) {
                o4[c].x *= corr; o4[c].y *= corr;
                o4[c].z *= corr; o4[c].w *= corr;
            }
#pragma unroll
            for (int jj = 0; jj < 16; jj++) {
                float p = exp2f(s[jj] - mnew);
                l += p;
                const float4* vr = (const float4*)&Vs[(js + jj) << 6];
#pragma unroll
                for (int c = 0; c < 16; c++) {
                    float4 vv = vr[c];
                    o4[c].x = fmaf(p, vv.x, o4[c].x);
                    o4[c].y = fmaf(p, vv.y, o4[c].y);
                    o4[c].z = fmaf(p, vv.z, o4[c].z);
                    o4[c].w = fmaf(p, vv.w, o4[c].w);
                }
            }
        }
    }

    const float inv = 1.0f / l;
    const int b = bh >> 4;
    const int h = bh & 15;
    float4* yout = (float4*)&g_y[((size_t)b * T_ + r) * D_ + h * HD_];
#pragma unroll
    for (int c = 0; c < 16; c++) {
        float4 w = o4[c];
        w.x *= inv; w.y *= inv; w.z *= inv; w.w *= inv;
        yout[c] = w;
    }
}

// ---------------------------------------------------------------------------
// Host launcher. ONLY harness pointers cross the host/device boundary.
// ---------------------------------------------------------------------------
extern "C" void kernel_launch(void* const* d_in, const int* in_sizes, int n_in,
                              void* d_out, int out_size)
{
    const float* x    = (const float*)d_in[0];
    const float* Wqkv = (const float*)d_in[1];
    const float* bqkv = (const float*)d_in[2];
    const float* Wout = (const float*)d_in[3];
    const float* bout = (const float*)d_in[4];
    float* out = (float*)d_out;

    // weight transpose + bf16 split (stateless, every call)
    convw_kernel<<<dim3(D3/32, D_/32), dim3(32, 8)>>>(Wqkv, D_, D3, 0);
    convw_kernel<<<dim3(D_/32, D_/32), dim3(32, 8)>>>(Wout, D_, D_, 1);

    // 1) QKV projection (WMMA) + bias + scatter to [B,H,T,HD]
    conva_kernel<<<(NTOK*D_/4 + 255)/256, 256>>>(x, NTOK*D_/4, 0);
    mma_gemm<<<dim3(D3/128, NTOK/128), 256>>>(bqkv, nullptr, D3, D_, 1);

    // 2) causal flash attention -> g_y
    attn_kernel<<<dim3(T_/AQ, B_*H_), 128>>>();

    // 3) output projection (WMMA) + bias
    conva_kernel<<<(NTOK*D_/4 + 255)/256, 256>>>(nullptr, NTOK*D_/4, 1);
    mma_gemm<<<dim3(D_/128, NTOK/128), 256>>>(bout, out, D_, D_, 2);
}

// round 14
// speedup vs baseline: 1.9902x; 1.1791x over previous
#include <cuda_runtime.h>
#include <cuda_bf16.h>
#include <mma.h>
#include <cstdint>

#define B_ 2
#define T_ 2048
#define D_ 1024
#define H_ 16
#define HD_ 64
#define NTOK (B_*T_)      // 4096
#define D3 (3*D_)         // 3072

using namespace nvcuda;

// ---------------------------------------------------------------------------
// Scratch (static device arrays: allocation-free).
// CRITICAL RULE (round-10 lesson): these symbols are NEVER passed as kernel
// arguments from host code. All access is from device code inside kernels.
// ---------------------------------------------------------------------------
__device__ float g_y[B_*T_*D_];           // attention output [B,T,D]

__device__ __nv_bfloat16 g_qh[B_*H_*T_*HD_], g_ql[B_*H_*T_*HD_]; // [bh,t,hd]
__device__ __nv_bfloat16 g_kh[B_*H_*T_*HD_], g_kl[B_*H_*T_*HD_]; // [bh,t,hd]
__device__ __nv_bfloat16 g_vth[B_*H_*T_*HD_], g_vtl[B_*H_*T_*HD_]; // [bh,hd,t]

__device__ __nv_bfloat16 g_Ah[NTOK*D_];   // activation hi/lo (x, then g_y)
__device__ __nv_bfloat16 g_Al[NTOK*D_];
__device__ __nv_bfloat16 g_Wh[D3*D_];     // Wqkv^T [N=3072,K=1024] hi/lo
__device__ __nv_bfloat16 g_Wl[D3*D_];
__device__ __nv_bfloat16 g_Uh[D_*D_];     // Wout^T [N=1024,K=1024] hi/lo
__device__ __nv_bfloat16 g_Ul[D_*D_];

// ---------------------------------------------------------------------------
// warp-level bf16 MMA m16n8k16 (baseline PTX)
// ---------------------------------------------------------------------------
#define MMA16816(c, a, b)                                                     \
    asm volatile("mma.sync.aligned.m16n8k16.row.col.f32.bf16.bf16.f32 "       \
        "{%0,%1,%2,%3}, {%4,%5,%6,%7}, {%8,%9}, {%0,%1,%2,%3};"               \
        : "+f"((c)[0]), "+f"((c)[1]), "+f"((c)[2]), "+f"((c)[3])              \
        : "r"((a)[0]), "r"((a)[1]), "r"((a)[2]), "r"((a)[3]),                 \
          "r"((b)[0]), "r"((b)[1]))

__device__ __forceinline__ void split2(float a, float b,
                                       uint32_t& hi, uint32_t& lo) {
    __nv_bfloat16 ah = __float2bfloat16(a), bh = __float2bfloat16(b);
    float ar = a - __bfloat162float(ah);
    float br = b - __bfloat162float(bh);
    __nv_bfloat162 h2 = __halves2bfloat162(ah, bh);
    __nv_bfloat162 l2 = __halves2bfloat162(__float2bfloat16(ar),
                                           __float2bfloat16(br));
    hi = *(uint32_t*)&h2;
    lo = *(uint32_t*)&l2;
}

// ---------------------------------------------------------------------------
// bf16 split conversions (scratch targets resolved DEVICE-SIDE via mode)
// ---------------------------------------------------------------------------
__global__ void conva_kernel(const float* __restrict__ A, int n4, int mode)
{
    int i = blockIdx.x * blockDim.x + threadIdx.x;
    if (i >= n4) return;
    const float* __restrict__ src = (mode == 0) ? A : g_y;
    float4 v = ((const float4*)src)[i];
    float xs[4] = {v.x, v.y, v.z, v.w};
    __nv_bfloat16 h[4], l[4];
#pragma unroll
    for (int j = 0; j < 4; j++) {
        h[j] = __float2bfloat16(xs[j]);
        l[j] = __float2bfloat16(xs[j] - __bfloat162float(h[j]));
    }
    __nv_bfloat162* Ah2 = (__nv_bfloat162*)g_Ah;
    __nv_bfloat162* Al2 = (__nv_bfloat162*)g_Al;
    Ah2[2*i+0] = __halves2bfloat162(h[0], h[1]);
    Ah2[2*i+1] = __halves2bfloat162(h[2], h[3]);
    Al2[2*i+0] = __halves2bfloat162(l[0], l[1]);
    Al2[2*i+1] = __halves2bfloat162(l[2], l[3]);
}

__global__ void convw_kernel(const float* __restrict__ W, int K, int N, int mode)
{
    __shared__ float t[32][33];
    __nv_bfloat16* __restrict__ Th = (mode == 0) ? g_Wh : g_Uh;
    __nv_bfloat16* __restrict__ Tl = (mode == 0) ? g_Wl : g_Ul;
    int n0 = blockIdx.x * 32, k0 = blockIdx.y * 32;
    int tx = threadIdx.x, ty = threadIdx.y;
#pragma unroll
    for (int i = 0; i < 4; i++)
        t[ty + i*8][tx] = W[(size_t)(k0 + ty + i*8) * N + n0 + tx];
    __syncthreads();
#pragma unroll
    for (int i = 0; i < 4; i++) {
        int n = n0 + ty + i*8, k = k0 + tx;
        float x = t[tx][ty + i*8];
        __nv_bfloat16 h = __float2bfloat16(x);
        __nv_bfloat16 l = __float2bfloat16(x - __bfloat162float(h));
        Th[(size_t)n * K + k] = h;
        Tl[(size_t)n * K + k] = l;
    }
}

// ---------------------------------------------------------------------------
// WMMA GEMM (unchanged from round-11 passing kernel except mode-1 epilogue
// now writes bf16 hi/lo Q/K and TRANSPOSED V directly).
// ---------------------------------------------------------------------------
#define GKC 32
#define G_LDS 40
#define G_TILE (128*G_LDS)

__global__ void __launch_bounds__(256)
mma_gemm(const float* __restrict__ bias, float* __restrict__ C,
         int N, int K, int mode)
{
    __shared__ __nv_bfloat16 sm[4 * G_TILE];   // 40960 B
    __nv_bfloat16* sAh = sm;
    __nv_bfloat16* sAl = sm + G_TILE;
    __nv_bfloat16* sBh = sm + 2*G_TILE;
    __nv_bfloat16* sBl = sm + 3*G_TILE;

    const int tid  = threadIdx.x;
    const int wid  = tid >> 5, lane = tid & 31;
    const int wM   = wid & 1,  wN = wid >> 1;
    const int m0   = blockIdx.y * 128, n0 = blockIdx.x * 128;

    const __nv_bfloat16* __restrict__ Bh = (mode == 1) ? g_Wh : g_Uh;
    const __nv_bfloat16* __restrict__ Bl = (mode == 1) ? g_Wl : g_Ul;

    const __nv_bfloat16* pAh = g_Ah + (size_t)m0 * K;
    const __nv_bfloat16* pAl = g_Al + (size_t)m0 * K;
    const __nv_bfloat16* pBh = Bh + (size_t)n0 * K;
    const __nv_bfloat16* pBl = Bl + (size_t)n0 * K;

    wmma::fragment<wmma::accumulator, 16, 16, 16, float> acc[4][2];
#pragma unroll
    for (int mt = 0; mt < 4; mt++)
#pragma unroll
        for (int nt = 0; nt < 2; nt++) wmma::fill_fragment(acc[mt][nt], 0.0f);

    uint4 rg[8];
#pragma unroll
    for (int r = 0; r < 2; r++) {
        int i = tid + r * 256, row = i >> 2, c8 = i & 3;
        size_t go = (size_t)row * K + c8 * 8;
        rg[r]     = *(const uint4*)(pAh + go);
        rg[2 + r] = *(const uint4*)(pAl + go);
        rg[4 + r] = *(const uint4*)(pBh + go);
        rg[6 + r] = *(const uint4*)(pBl + go);
    }

    const int nch = K / GKC;
    for (int ch = 0; ch < nch; ch++) {
        __syncthreads();
#pragma unroll
        for (int r = 0; r < 2; r++) {
            int i = tid + r * 256, row = i >> 2, c8 = i & 3;
            int so = row * G_LDS + c8 * 8;
            *(uint4*)(sAh + so) = rg[r];
            *(uint4*)(sAl + so) = rg[2 + r];
            *(uint4*)(sBh + so) = rg[4 + r];
            *(uint4*)(sBl + so) = rg[6 + r];
        }
        __syncthreads();

        if (ch + 1 < nch) {
            int kc = (ch + 1) * GKC;
#pragma unroll
            for (int r = 0; r < 2; r++) {
                int i = tid + r * 256, row = i >> 2, c8 = i & 3;
                size_t go = (size_t)row * K + kc + c8 * 8;
                rg[r]     = *(const uint4*)(pAh + go);
                rg[2 + r] = *(const uint4*)(pAl + go);
                rg[4 + r] = *(const uint4*)(pBh + go);
                rg[6 + r] = *(const uint4*)(pBl + go);
            }
        }

#pragma unroll
        for (int ks = 0; ks < 2; ks++) {
            const int k0 = ks * 16;
            wmma::fragment<wmma::matrix_a, 16, 16, 16, __nv_bfloat16,
                           wmma::row_major> ah[4], al[4];
            wmma::fragment<wmma::matrix_b, 16, 16, 16, __nv_bfloat16,
                           wmma::col_major> bh[2], bl[2];
#pragma unroll
            for (int mt = 0; mt < 4; mt++) {
                int rb = wM * 64 + mt * 16;
                wmma::load_matrix_sync(ah[mt], sAh + rb * G_LDS + k0, G_LDS);
                wmma::load_matrix_sync(al[mt], sAl + rb * G_LDS + k0, G_LDS);
            }
#pragma unroll
            for (int nt = 0; nt < 2; nt++) {
                int nb = wN * 32 + nt * 16;
                wmma::load_matrix_sync(bh[nt], sBh + nb * G_LDS + k0, G_LDS);
                wmma::load_matrix_sync(bl[nt], sBl + nb * G_LDS + k0, G_LDS);
            }
#pragma unroll
            for (int mt = 0; mt < 4; mt++)
#pragma unroll
                for (int nt = 0; nt < 2; nt++) {
                    wmma::mma_sync(acc[mt][nt], ah[mt], bh[nt], acc[mt][nt]);
                    wmma::mma_sync(acc[mt][nt], ah[mt], bl[nt], acc[mt][nt]);
                    wmma::mma_sync(acc[mt][nt], al[mt], bh[nt], acc[mt][nt]);
                }
        }
    }

    __syncthreads();
    float* scratch = (float*)sm + wid * 256;
#pragma unroll
    for (int mt = 0; mt < 4; mt++) {
#pragma unroll
        for (int nt = 0; nt < 2; nt++) {
            wmma::store_matrix_sync(scratch, acc[mt][nt], 16, wmma::mem_row_major);
            __syncwarp();
            int row0 = m0 + wM * 64 + mt * 16;
            int col0 = n0 + wN * 32 + nt * 16;
#pragma unroll
            for (int e = lane; e < 256; e += 32) {
                int rr = e >> 4, cc = e & 15;
                int r = row0 + rr, col = col0 + cc;
                float v = scratch[e] + bias[col];
                if (mode == 1) {
                    int which = col >> 10;
                    int rem   = col & 1023;
                    int h     = rem >> 6;
                    int hd    = rem & 63;
                    int b     = r / T_;
                    int t     = r - b * T_;
                    int bhh   = b * H_ + h;
                    __nv_bfloat16 vh = __float2bfloat16(v);
                    __nv_bfloat16 vl = __float2bfloat16(v - __bfloat162float(vh));
                    if (which == 0) {
                        size_t idx = ((size_t)bhh * T_ + t) * HD_ + hd;
                        g_qh[idx] = vh; g_ql[idx] = vl;
                    } else if (which == 1) {
                        size_t idx = ((size_t)bhh * T_ + t) * HD_ + hd;
                        g_kh[idx] = vh; g_kl[idx] = vl;
                    } else {
                        size_t idx = ((size_t)bhh * HD_ + hd) * T_ + t;
                        g_vth[idx] = vh; g_vtl[idx] = vl;
                    }
                } else {
                    C[(size_t)r * N + col] = v;
                }
            }
            __syncwarp();
        }
    }
}

// ---------------------------------------------------------------------------
// Tensor-core causal flash attention (FA2-style, register-resident).
// Grid (T/64, B*H), 128 threads = 4 independent warps; warp owns 16 q-rows.
// No smem, no __syncthreads. Fragments loaded directly from gmem as u32
// pairs (m16n8k16 layouts). S: 3-pass hi/lo; softmax in regs (quad shfl);
// P repacked in-register as bf16 hi/lo a-frags; PV: 3-pass with transposed V.
// ---------------------------------------------------------------------------
__global__ void __launch_bounds__(128)
attn_mma_kernel()
{
    const int tid  = threadIdx.x;
    const int wid  = tid >> 5, lane = tid & 31;
    const int grp  = lane >> 2, t2 = lane & 3;
    const int bh   = blockIdx.y;
    const int qw   = blockIdx.x * 64 + wid * 16;   // warp q-row base
    const int rA   = qw + grp;                     // rows rA and rA+8
    const float scl2 = 0.125f * 1.4426950408889634f;  // scale * log2(e)

    const __nv_bfloat16* __restrict__ Qh = g_qh + (size_t)bh * (T_*HD_);
    const __nv_bfloat16* __restrict__ Ql = g_ql + (size_t)bh * (T_*HD_);
    const __nv_bfloat16* __restrict__ Kh = g_kh + (size_t)bh * (T_*HD_);
    const __nv_bfloat16* __restrict__ Kl = g_kl + (size_t)bh * (T_*HD_);
    const __nv_bfloat16* __restrict__ Vh = g_vth + (size_t)bh * (HD_*T_);
    const __nv_bfloat16* __restrict__ Vl = g_vtl + (size_t)bh * (HD_*T_);

    // Q a-fragments (4 d-steps, hi/lo), loaded once
    uint32_t qah[4][4], qal[4][4];
#pragma unroll
    for (int kd = 0; kd < 4; kd++) {
        int d = kd * 16 + t2 * 2;
        qah[kd][0] = *(const uint32_t*)&Qh[(size_t)rA * HD_ + d];
        qah[kd][1] = *(const uint32_t*)&Qh[(size_t)(rA+8) * HD_ + d];
        qah[kd][2] = *(const uint32_t*)&Qh[(size_t)rA * HD_ + d + 8];
        qah[kd][3] = *(const uint32_t*)&Qh[(size_t)(rA+8) * HD_ + d + 8];
        qal[kd][0] = *(const uint32_t*)&Ql[(size_t)rA * HD_ + d];
        qal[kd][1] = *(const uint32_t*)&Ql[(size_t)(rA+8) * HD_ + d];
        qal[kd][2] = *(const uint32_t*)&Ql[(size_t)rA * HD_ + d + 8];
        qal[kd][3] = *(const uint32_t*)&Ql[(size_t)(rA+8) * HD_ + d + 8];
    }

    float o[8][4];                                  // 8 dim-tiles x c[4]
#pragma unroll
    for (int dt = 0; dt < 8; dt++)
#pragma unroll
        for (int q = 0; q < 4; q++) o[dt][q] = 0.f;
    float mA = -1e30f, mB = -1e30f, lA = 0.f, lB = 0.f;

    const int nch = (qw + 47) >> 5;                 // causal chunk count
    for (int ch = 0; ch < nch; ch++) {
        const int j0 = ch << 5;

        // ---- S = Q K^T (3-pass hi/lo), 4 n-tiles of 8 keys ----
        float s[4][4];
#pragma unroll
        for (int nt = 0; nt < 4; nt++)
#pragma unroll
            for (int q = 0; q < 4; q++) s[nt][q] = 0.f;
#pragma unroll
        for (int kd = 0; kd < 4; kd++) {
            int d = kd * 16 + t2 * 2;
#pragma unroll
            for (int nt = 0; nt < 4; nt++) {
                int key = j0 + nt * 8 + grp;
                const __nv_bfloat16* kp = &Kh[(size_t)key * HD_ + d];
                const __nv_bfloat16* kq = &Kl[(size_t)key * HD_ + d];
                uint32_t kb[2]  = { *(const uint32_t*)kp,
                                    *(const uint32_t*)(kp + 8) };
                uint32_t kbl[2] = { *(const uint32_t*)kq,
                                    *(const uint32_t*)(kq + 8) };
                MMA16816(s[nt], qah[kd], kb);
                MMA16816(s[nt], qah[kd], kbl);
                MMA16816(s[nt], qal[kd], kb);
            }
        }

        // ---- scale + causal mask (in place) ----
#pragma unroll
        for (int nt = 0; nt < 4; nt++) {
            int k0 = j0 + nt * 8 + t2 * 2;
            s[nt][0] = (k0     <= rA    ) ? s[nt][0] * scl2 : -1e30f;
            s[nt][1] = (k0 + 1 <= rA    ) ? s[nt][1] * scl2 : -1e30f;
            s[nt][2] = (k0     <= rA + 8) ? s[nt][2] * scl2 : -1e30f;
            s[nt][3] = (k0 + 1 <= rA + 8) ? s[nt][3] * scl2 : -1e30f;
        }

        // ---- online softmax (register-resident, quad shfl) ----
        float mxA = fmaxf(fmaxf(s[0][0], s[0][1]), fmaxf(s[1][0], s[1][1]));
        mxA = fmaxf(mxA, fmaxf(fmaxf(s[2][0], s[2][1]), fmaxf(s[3][0], s[3][1])));
        float mxB = fmaxf(fmaxf(s[0][2], s[0][3]), fmaxf(s[1][2], s[1][3]));
        mxB = fmaxf(mxB, fmaxf(fmaxf(s[2][2], s[2][3]), fmaxf(s[3][2], s[3][3])));
        mxA = fmaxf(mxA, __shfl_xor_sync(0xffffffffu, mxA, 1));
        mxA = fmaxf(mxA, __shfl_xor_sync(0xffffffffu, mxA, 2));
        mxB = fmaxf(mxB, __shfl_xor_sync(0xffffffffu, mxB, 1));
        mxB = fmaxf(mxB, __shfl_xor_sync(0xffffffffu, mxB, 2));
        float mnA = fmaxf(mA, mxA), mnB = fmaxf(mB, mxB);
        float corrA = exp2f(mA - mnA), corrB = exp2f(mB - mnB);
        mA = mnA; mB = mnB;
        lA *= corrA; lB *= corrB;
#pragma unroll
        for (int nt = 0; nt < 4; nt++) {
            s[nt][0] = exp2f(s[nt][0] - mA);
            s[nt][1] = exp2f(s[nt][1] - mA);
            s[nt][2] = exp2f(s[nt][2] - mB);
            s[nt][3] = exp2f(s[nt][3] - mB);
            lA += s[nt][0] + s[nt][1];
            lB += s[nt][2] + s[nt][3];
        }
#pragma unroll
        for (int dt = 0; dt < 8; dt++) {
            o[dt][0] *= corrA; o[dt][1] *= corrA;
            o[dt][2] *= corrB; o[dt][3] *= corrB;
        }

        // ---- repack P as bf16 hi/lo a-frags (2 k-steps of 16 keys) ----
        uint32_t pah[2][4], pal[2][4];
#pragma unroll
        for (int ks = 0; ks < 2; ks++) {
            split2(s[2*ks][0],   s[2*ks][1],   pah[ks][0], pal[ks][0]);
            split2(s[2*ks][2],   s[2*ks][3],   pah[ks][1], pal[ks][1]);
            split2(s[2*ks+1][0], s[2*ks+1][1], pah[ks][2], pal[ks][2]);
            split2(s[2*ks+1][2], s[2*ks+1][3], pah[ks][3], pal[ks][3]);
        }

        // ---- O += P V (3-pass hi/lo), V transposed [hd][T] ----
#pragma unroll
        for (int ks = 0; ks < 2; ks++) {
            int key = j0 + ks * 16 + t2 * 2;
#pragma unroll
            for (int dt = 0; dt < 8; dt++) {
                int dim = dt * 8 + grp;
                const __nv_bfloat16* vp = &Vh[(size_t)dim * T_ + key];
                const __nv_bfloat16* vq = &Vl[(size_t)dim * T_ + key];
                uint32_t vb[2]  = { *(const uint32_t*)vp,
                                    *(const uint32_t*)(vp + 8) };
                uint32_t vbl[2] = { *(const uint32_t*)vq,
                                    *(const uint32_t*)(vq + 8) };
                MMA16816(o[dt], pah[ks], vb);
                MMA16816(o[dt], pal[ks], vb);
                MMA16816(o[dt], pah[ks], vbl);
            }
        }
    }

    // ---- finalize: reduce l over quad, normalize, write g_y ----
    lA += __shfl_xor_sync(0xffffffffu, lA, 1);
    lA += __shfl_xor_sync(0xffffffffu, lA, 2);
    lB += __shfl_xor_sync(0xffffffffu, lB, 1);
    lB += __shfl_xor_sync(0xffffffffu, lB, 2);
    const float invA = 1.0f / lA, invB = 1.0f / lB;
    const int b = bh >> 4, h = bh & 15;
    float* yA = &g_y[((size_t)b * T_ + rA) * D_ + h * HD_];
    float* yB = &g_y[((size_t)b * T_ + rA + 8) * D_ + h * HD_];
#pragma unroll
    for (int dt = 0; dt < 8; dt++) {
        int d = dt * 8 + t2 * 2;
        *(float2*)&yA[d] = make_float2(o[dt][0] * invA, o[dt][1] * invA);
        *(float2*)&yB[d] = make_float2(o[dt][2] * invB, o[dt][3] * invB);
    }
}

// ---------------------------------------------------------------------------
// Host launcher. ONLY harness pointers cross the host/device boundary.
// ---------------------------------------------------------------------------
extern "C" void kernel_launch(void* const* d_in, const int* in_sizes, int n_in,
                              void* d_out, int out_size)
{
    const float* x    = (const float*)d_in[0];
    const float* Wqkv = (const float*)d_in[1];
    const float* bqkv = (const float*)d_in[2];
    const float* Wout = (const float*)d_in[3];
    const float* bout = (const float*)d_in[4];
    float* out = (float*)d_out;

    // weight transpose + bf16 split (stateless, every call)
    convw_kernel<<<dim3(D3/32, D_/32), dim3(32, 8)>>>(Wqkv, D_, D3, 0);
    convw_kernel<<<dim3(D_/32, D_/32), dim3(32, 8)>>>(Wout, D_, D_, 1);

    // 1) QKV projection (WMMA) -> bf16 hi/lo Q,K and transposed V
    conva_kernel<<<(NTOK*D_/4 + 255)/256, 256>>>(x, NTOK*D_/4, 0);
    mma_gemm<<<dim3(D3/128, NTOK/128), 256>>>(bqkv, nullptr, D3, D_, 1);

    // 2) tensor-core causal flash attention -> g_y
    attn_mma_kernel<<<dim3(T_/64, B_*H_), 128>>>();

    // 3) output projection (WMMA) + bias
    conva_kernel<<<(NTOK*D_/4 + 255)/256, 256>>>(nullptr, NTOK*D_/4, 1);
    mma_gemm<<<dim3(D_/128, NTOK/128), 256>>>(bout, out, D_, D_, 2);
}

// round 15
// speedup vs baseline: 2.0153x; 1.0126x over previous
#include <cuda_runtime.h>
#include <cuda_bf16.h>
#include <mma.h>
#include <cstdint>

#define B_ 2
#define T_ 2048
#define D_ 1024
#define H_ 16
#define HD_ 64
#define NTOK (B_*T_)      // 4096
#define D3 (3*D_)         // 3072

using namespace nvcuda;

// ---------------------------------------------------------------------------
// Scratch (static device arrays: allocation-free).
// CRITICAL RULE (round-10 lesson): these symbols are NEVER passed as kernel
// arguments from host code. All access is from device code inside kernels.
// ---------------------------------------------------------------------------
__device__ __nv_bfloat16 g_qh[B_*H_*T_*HD_], g_ql[B_*H_*T_*HD_]; // [bh,t,hd]
__device__ __nv_bfloat16 g_kh[B_*H_*T_*HD_], g_kl[B_*H_*T_*HD_]; // [bh,t,hd]
__device__ __nv_bfloat16 g_vth[B_*H_*T_*HD_], g_vtl[B_*H_*T_*HD_]; // [bh,hd,t]

__device__ __nv_bfloat16 g_Ah[NTOK*D_];   // activation hi/lo (x, then attn out)
__device__ __nv_bfloat16 g_Al[NTOK*D_];
__device__ __nv_bfloat16 g_Wh[D3*D_];     // Wqkv^T [N=3072,K=1024] hi/lo
__device__ __nv_bfloat16 g_Wl[D3*D_];
__device__ __nv_bfloat16 g_Uh[D_*D_];     // Wout^T [N=1024,K=1024] hi/lo
__device__ __nv_bfloat16 g_Ul[D_*D_];

// ---------------------------------------------------------------------------
// warp-level bf16 MMA m16n8k16 (baseline PTX)
// ---------------------------------------------------------------------------
#define MMA16816(c, a, b)                                                     \
    asm volatile("mma.sync.aligned.m16n8k16.row.col.f32.bf16.bf16.f32 "       \
        "{%0,%1,%2,%3}, {%4,%5,%6,%7}, {%8,%9}, {%0,%1,%2,%3};"               \
        : "+f"((c)[0]), "+f"((c)[1]), "+f"((c)[2]), "+f"((c)[3])              \
        : "r"((a)[0]), "r"((a)[1]), "r"((a)[2]), "r"((a)[3]),                 \
          "r"((b)[0]), "r"((b)[1]))

__device__ __forceinline__ void split2(float a, float b,
                                       uint32_t& hi, uint32_t& lo) {
    __nv_bfloat16 ah = __float2bfloat16(a), bh = __float2bfloat16(b);
    float ar = a - __bfloat162float(ah);
    float br = b - __bfloat162float(bh);
    __nv_bfloat162 h2 = __halves2bfloat162(ah, bh);
    __nv_bfloat162 l2 = __halves2bfloat162(__float2bfloat16(ar),
                                           __float2bfloat16(br));
    hi = *(uint32_t*)&h2;
    lo = *(uint32_t*)&l2;
}

// ---------------------------------------------------------------------------
// bf16 split conversions (scratch targets resolved DEVICE-SIDE)
// ---------------------------------------------------------------------------
__global__ void conva_kernel(const float* __restrict__ A, int n4)
{
    int i = blockIdx.x * blockDim.x + threadIdx.x;
    if (i >= n4) return;
    float4 v = ((const float4*)A)[i];
    float xs[4] = {v.x, v.y, v.z, v.w};
    __nv_bfloat16 h[4], l[4];
#pragma unroll
    for (int j = 0; j < 4; j++) {
        h[j] = __float2bfloat16(xs[j]);
        l[j] = __float2bfloat16(xs[j] - __bfloat162float(h[j]));
    }
    __nv_bfloat162* Ah2 = (__nv_bfloat162*)g_Ah;
    __nv_bfloat162* Al2 = (__nv_bfloat162*)g_Al;
    Ah2[2*i+0] = __halves2bfloat162(h[0], h[1]);
    Ah2[2*i+1] = __halves2bfloat162(h[2], h[3]);
    Al2[2*i+0] = __halves2bfloat162(l[0], l[1]);
    Al2[2*i+1] = __halves2bfloat162(l[2], l[3]);
}

__global__ void convw_kernel(const float* __restrict__ W, int K, int N, int mode)
{
    __shared__ float t[32][33];
    __nv_bfloat16* __restrict__ Th = (mode == 0) ? g_Wh : g_Uh;
    __nv_bfloat16* __restrict__ Tl = (mode == 0) ? g_Wl : g_Ul;
    int n0 = blockIdx.x * 32, k0 = blockIdx.y * 32;
    int tx = threadIdx.x, ty = threadIdx.y;
#pragma unroll
    for (int i = 0; i < 4; i++)
        t[ty + i*8][tx] = W[(size_t)(k0 + ty + i*8) * N + n0 + tx];
    __syncthreads();
#pragma unroll
    for (int i = 0; i < 4; i++) {
        int n = n0 + ty + i*8, k = k0 + tx;
        float x = t[tx][ty + i*8];
        __nv_bfloat16 h = __float2bfloat16(x);
        __nv_bfloat16 l = __float2bfloat16(x - __bfloat162float(h));
        Th[(size_t)n * K + k] = h;
        Tl[(size_t)n * K + k] = l;
    }
}

// ---------------------------------------------------------------------------
// WMMA GEMM: C[M,N] = split(A[M,K]) @ split(B[N,K])^T + bias
// v2: 512 threads = 16 warps (4x4 grid), warp tile 32x32 (2x2 wmma tiles).
// Same 128x128 CTA tile / 40KB smem / 3-pass hi-lo math as the round-14
// winner, but 2x the warps per SM (occ 12.5% -> ~25%) to cover LDSM->HMMA
// latency (measured issue=17%, tensor=36% at 8 warps).
// mode 1: scatter bf16 hi/lo Q,K + transposed V     mode 2: write C (f32)
// ---------------------------------------------------------------------------
#define GKC 32
#define G_LDS 40
#define G_TILE (128*G_LDS)

__global__ void __launch_bounds__(512)
mma_gemm(const float* __restrict__ bias, float* __restrict__ C,
         int N, int K, int mode)
{
    __shared__ __nv_bfloat16 sm[4 * G_TILE];   // 40960 B
    __nv_bfloat16* sAh = sm;
    __nv_bfloat16* sAl = sm + G_TILE;
    __nv_bfloat16* sBh = sm + 2*G_TILE;
    __nv_bfloat16* sBl = sm + 3*G_TILE;

    const int tid  = threadIdx.x;
    const int wid  = tid >> 5, lane = tid & 31;
    const int wM   = wid & 3,  wN = wid >> 2;     // 4 x 4 warp grid
    const int m0   = blockIdx.y * 128, n0 = blockIdx.x * 128;

    const __nv_bfloat16* __restrict__ Bh = (mode == 1) ? g_Wh : g_Uh;
    const __nv_bfloat16* __restrict__ Bl = (mode == 1) ? g_Wl : g_Ul;

    const __nv_bfloat16* pAh = g_Ah + (size_t)m0 * K;
    const __nv_bfloat16* pAl = g_Al + (size_t)m0 * K;
    const __nv_bfloat16* pBh = Bh + (size_t)n0 * K;
    const __nv_bfloat16* pBl = Bl + (size_t)n0 * K;

    wmma::fragment<wmma::accumulator, 16, 16, 16, float> acc[2][2];
#pragma unroll
    for (int mt = 0; mt < 2; mt++)
#pragma unroll
        for (int nt = 0; nt < 2; nt++) wmma::fill_fragment(acc[mt][nt], 0.0f);

    // per-chunk gmem staging: 4 arrays x 1 uint4 per thread
    // (tile per array = 128 rows x 32 cols bf16 = 512 uint4; 512 threads)
    const int srow = tid >> 2, sc8 = tid & 3;
    uint4 rg[4];
    {
        size_t go = (size_t)srow * K + sc8 * 8;
        rg[0] = *(const uint4*)(pAh + go);
        rg[1] = *(const uint4*)(pAl + go);
        rg[2] = *(const uint4*)(pBh + go);
        rg[3] = *(const uint4*)(pBl + go);
    }

    const int nch = K / GKC;
    for (int ch = 0; ch < nch; ch++) {
        __syncthreads();                       // prev chunk's compute done
        {
            int so = srow * G_LDS + sc8 * 8;
            *(uint4*)(sAh + so) = rg[0];
            *(uint4*)(sAl + so) = rg[1];
            *(uint4*)(sBh + so) = rg[2];
            *(uint4*)(sBl + so) = rg[3];
        }
        __syncthreads();

        if (ch + 1 < nch) {                    // prefetch next chunk
            size_t go = (size_t)srow * K + (ch + 1) * GKC + sc8 * 8;
            rg[0] = *(const uint4*)(pAh + go);
            rg[1] = *(const uint4*)(pAl + go);
            rg[2] = *(const uint4*)(pBh + go);
            rg[3] = *(const uint4*)(pBl + go);
        }

#pragma unroll
        for (int ks = 0; ks < 2; ks++) {
            const int k0 = ks * 16;
            wmma::fragment<wmma::matrix_a, 16, 16, 16, __nv_bfloat16,
                           wmma::row_major> ah[2], al[2];
            wmma::fragment<wmma::matrix_b, 16, 16, 16, __nv_bfloat16,
                           wmma::col_major> bh[2], bl[2];
#pragma unroll
            for (int mt = 0; mt < 2; mt++) {
                int rb = wM * 32 + mt * 16;
                wmma::load_matrix_sync(ah[mt], sAh + rb * G_LDS + k0, G_LDS);
                wmma::load_matrix_sync(al[mt], sAl + rb * G_LDS + k0, G_LDS);
            }
#pragma unroll
            for (int nt = 0; nt < 2; nt++) {
                int nb = wN * 32 + nt * 16;
                wmma::load_matrix_sync(bh[nt], sBh + nb * G_LDS + k0, G_LDS);
                wmma::load_matrix_sync(bl[nt], sBl + nb * G_LDS + k0, G_LDS);
            }
#pragma unroll
            for (int mt = 0; mt < 2; mt++)
#pragma unroll
                for (int nt = 0; nt < 2; nt++) {
                    wmma::mma_sync(acc[mt][nt], ah[mt], bh[nt], acc[mt][nt]);
                    wmma::mma_sync(acc[mt][nt], ah[mt], bl[nt], acc[mt][nt]);
                    wmma::mma_sync(acc[mt][nt], al[mt], bh[nt], acc[mt][nt]);
                }
        }
    }

    // epilogue: reuse tile smem as per-warp 16x16 float scratch (16KB)
    __syncthreads();
    float* scratch = (float*)sm + wid * 256;
#pragma unroll
    for (int mt = 0; mt < 2; mt++) {
#pragma unroll
        for (int nt = 0; nt < 2; nt++) {
            wmma::store_matrix_sync(scratch, acc[mt][nt], 16, wmma::mem_row_major);
            __syncwarp();
            int row0 = m0 + wM * 32 + mt * 16;
            int col0 = n0 + wN * 32 + nt * 16;
#pragma unroll
            for (int e = lane; e < 256; e += 32) {
                int rr = e >> 4, cc = e & 15;
                int r = row0 + rr, col = col0 + cc;
                float v = scratch[e] + bias[col];
                if (mode == 1) {
                    int which = col >> 10;
                    int rem   = col & 1023;
                    int h     = rem >> 6;
                    int hd    = rem & 63;
                    int b     = r / T_;
                    int t     = r - b * T_;
                    int bhh   = b * H_ + h;
                    __nv_bfloat16 vh = __float2bfloat16(v);
                    __nv_bfloat16 vl = __float2bfloat16(v - __bfloat162float(vh));
                    if (which == 0) {
                        size_t idx = ((size_t)bhh * T_ + t) * HD_ + hd;
                        g_qh[idx] = vh; g_ql[idx] = vl;
                    } else if (which == 1) {
                        size_t idx = ((size_t)bhh * T_ + t) * HD_ + hd;
                        g_kh[idx] = vh; g_kl[idx] = vl;
                    } else {
                        size_t idx = ((size_t)bhh * HD_ + hd) * T_ + t;
                        g_vth[idx] = vh; g_vtl[idx] = vl;
                    }
                } else {
                    C[(size_t)r * N + col] = v;
                }
            }
            __syncwarp();
        }
    }
}

// ---------------------------------------------------------------------------
// Tensor-core causal flash attention — byte-identical to the round-14 winner
// except the finalize writes bf16 hi/lo g_Ah/g_Al directly (fuses away the
// f32 g_y round-trip and the second conva pass).
// ---------------------------------------------------------------------------
__global__ void __launch_bounds__(128)
attn_mma_kernel()
{
    const int tid  = threadIdx.x;
    const int wid  = tid >> 5, lane = tid & 31;
    const int grp  = lane >> 2, t2 = lane & 3;
    const int bh   = blockIdx.y;
    const int qw   = blockIdx.x * 64 + wid * 16;   // warp q-row base
    const int rA   = qw + grp;                     // rows rA and rA+8
    const float scl2 = 0.125f * 1.4426950408889634f;  // scale * log2(e)

    const __nv_bfloat16* __restrict__ Qh = g_qh + (size_t)bh * (T_*HD_);
    const __nv_bfloat16* __restrict__ Ql = g_ql + (size_t)bh * (T_*HD_);
    const __nv_bfloat16* __restrict__ Kh = g_kh + (size_t)bh * (T_*HD_);
    const __nv_bfloat16* __restrict__ Kl = g_kl + (size_t)bh * (T_*HD_);
    const __nv_bfloat16* __restrict__ Vh = g_vth + (size_t)bh * (HD_*T_);
    const __nv_bfloat16* __restrict__ Vl = g_vtl + (size_t)bh * (HD_*T_);

    uint32_t qah[4][4], qal[4][4];
#pragma unroll
    for (int kd = 0; kd < 4; kd++) {
        int d = kd * 16 + t2 * 2;
        qah[kd][0] = *(const uint32_t*)&Qh[(size_t)rA * HD_ + d];
        qah[kd][1] = *(const uint32_t*)&Qh[(size_t)(rA+8) * HD_ + d];
        qah[kd][2] = *(const uint32_t*)&Qh[(size_t)rA * HD_ + d + 8];
        qah[kd][3] = *(const uint32_t*)&Qh[(size_t)(rA+8) * HD_ + d + 8];
        qal[kd][0] = *(const uint32_t*)&Ql[(size_t)rA * HD_ + d];
        qal[kd][1] = *(const uint32_t*)&Ql[(size_t)(rA+8) * HD_ + d];
        qal[kd][2] = *(const uint32_t*)&Ql[(size_t)rA * HD_ + d + 8];
        qal[kd][3] = *(const uint32_t*)&Ql[(size_t)(rA+8) * HD_ + d + 8];
    }

    float o[8][4];
#pragma unroll
    for (int dt = 0; dt < 8; dt++)
#pragma unroll
        for (int q = 0; q < 4; q++) o[dt][q] = 0.f;
    float mA = -1e30f, mB = -1e30f, lA = 0.f, lB = 0.f;

    const int nch = (qw + 47) >> 5;
    for (int ch = 0; ch < nch; ch++) {
        const int j0 = ch << 5;

        float s[4][4];
#pragma unroll
        for (int nt = 0; nt < 4; nt++)
#pragma unroll
            for (int q = 0; q < 4; q++) s[nt][q] = 0.f;
#pragma unroll
        for (int kd = 0; kd < 4; kd++) {
            int d = kd * 16 + t2 * 2;
#pragma unroll
            for (int nt = 0; nt < 4; nt++) {
                int key = j0 + nt * 8 + grp;
                const __nv_bfloat16* kp = &Kh[(size_t)key * HD_ + d];
                const __nv_bfloat16* kq = &Kl[(size_t)key * HD_ + d];
                uint32_t kb[2]  = { *(const uint32_t*)kp,
                                    *(const uint32_t*)(kp + 8) };
                uint32_t kbl[2] = { *(const uint32_t*)kq,
                                    *(const uint32_t*)(kq + 8) };
                MMA16816(s[nt], qah[kd], kb);
                MMA16816(s[nt], qah[kd], kbl);
                MMA16816(s[nt], qal[kd], kb);
            }
        }

#pragma unroll
        for (int nt = 0; nt < 4; nt++) {
            int k0 = j0 + nt * 8 + t2 * 2;
            s[nt][0] = (k0     <= rA    ) ? s[nt][0] * scl2 : -1e30f;
            s[nt][1] = (k0 + 1 <= rA    ) ? s[nt][1] * scl2 : -1e30f;
            s[nt][2] = (k0     <= rA + 8) ? s[nt][2] * scl2 : -1e30f;
            s[nt][3] = (k0 + 1 <= rA + 8) ? s[nt][3] * scl2 : -1e30f;
        }

        float mxA = fmaxf(fmaxf(s[0][0], s[0][1]), fmaxf(s[1][0], s[1][1]));
        mxA = fmaxf(mxA, fmaxf(fmaxf(s[2][0], s[2][1]), fmaxf(s[3][0], s[3][1])));
        float mxB = fmaxf(fmaxf(s[0][2], s[0][3]), fmaxf(s[1][2], s[1][3]));
        mxB = fmaxf(mxB, fmaxf(fmaxf(s[2][2], s[2][3]), fmaxf(s[3][2], s[3][3])));
        mxA = fmaxf(mxA, __shfl_xor_sync(0xffffffffu, mxA, 1));
        mxA = fmaxf(mxA, __shfl_xor_sync(0xffffffffu, mxA, 2));
        mxB = fmaxf(mxB, __shfl_xor_sync(0xffffffffu, mxB, 1));
        mxB = fmaxf(mxB, __shfl_xor_sync(0xffffffffu, mxB, 2));
        float mnA = fmaxf(mA, mxA), mnB = fmaxf(mB, mxB);
        float corrA = exp2f(mA - mnA), corrB = exp2f(mB - mnB);
        mA = mnA; mB = mnB;
        lA *= corrA; lB *= corrB;
#pragma unroll
        for (int nt = 0; nt < 4; nt++) {
            s[nt][0] = exp2f(s[nt][0] - mA);
            s[nt][1] = exp2f(s[nt][1] - mA);
            s[nt][2] = exp2f(s[nt][2] - mB);
            s[nt][3] = exp2f(s[nt][3] - mB);
            lA += s[nt][0] + s[nt][1];
            lB += s[nt][2] + s[nt][3];
        }
#pragma unroll
        for (int dt = 0; dt < 8; dt++) {
            o[dt][0] *= corrA; o[dt][1] *= corrA;
            o[dt][2] *= corrB; o[dt][3] *= corrB;
        }

        uint32_t pah[2][4], pal[2][4];
#pragma unroll
        for (int ks = 0; ks < 2; ks++) {
            split2(s[2*ks][0],   s[2*ks][1],   pah[ks][0], pal[ks][0]);
            split2(s[2*ks][2],   s[2*ks][3],   pah[ks][1], pal[ks][1]);
            split2(s[2*ks+1][0], s[2*ks+1][1], pah[ks][2], pal[ks][2]);
            split2(s[2*ks+1][2], s[2*ks+1][3], pah[ks][3], pal[ks][3]);
        }

#pragma unroll
        for (int ks = 0; ks < 2; ks++) {
            int key = j0 + ks * 16 + t2 * 2;
#pragma unroll
            for (int dt = 0; dt < 8; dt++) {
                int dim = dt * 8 + grp;
                const __nv_bfloat16* vp = &Vh[(size_t)dim * T_ + key];
                const __nv_bfloat16* vq = &Vl[(size_t)dim * T_ + key];
                uint32_t vb[2]  = { *(const uint32_t*)vp,
                                    *(const uint32_t*)(vp + 8) };
                uint32_t vbl[2] = { *(const uint32_t*)vq,
                                    *(const uint32_t*)(vq + 8) };
                MMA16816(o[dt], pah[ks], vb);
                MMA16816(o[dt], pal[ks], vb);
                MMA16816(o[dt], pah[ks], vbl);
            }
        }
    }

    // finalize: reduce l over quad, normalize, write bf16 hi/lo g_Ah/g_Al
    lA += __shfl_xor_sync(0xffffffffu, lA, 1);
    lA += __shfl_xor_sync(0xffffffffu, lA, 2);
    lB += __shfl_xor_sync(0xffffffffu, lB, 1);
    lB += __shfl_xor_sync(0xffffffffu, lB, 2);
    const float invA = 1.0f / lA, invB = 1.0f / lB;
    const int b = bh >> 4, h = bh & 15;
    const size_t baseA = ((size_t)b * T_ + rA) * D_ + h * HD_;
    const size_t baseB = ((size_t)b * T_ + rA + 8) * D_ + h * HD_;
#pragma unroll
    for (int dt = 0; dt < 8; dt++) {
        int d = dt * 8 + t2 * 2;
        uint32_t hA, lAo, hB, lBo;
        split2(o[dt][0] * invA, o[dt][1] * invA, hA, lAo);
        split2(o[dt][2] * invB, o[dt][3] * invB, hB, lBo);
        *(uint32_t*)&g_Ah[baseA + d] = hA;
        *(uint32_t*)&g_Al[baseA + d] = lAo;
        *(uint32_t*)&g_Ah[baseB + d] = hB;
        *(uint32_t*)&g_Al[baseB + d] = lBo;
    }
}

// ---------------------------------------------------------------------------
// Host launcher. ONLY harness pointers cross the host/device boundary.
// ---------------------------------------------------------------------------
extern "C" void kernel_launch(void* const* d_in, const int* in_sizes, int n_in,
                              void* d_out, int out_size)
{
    const float* x    = (const float*)d_in[0];
    const float* Wqkv = (const float*)d_in[1];
    const float* bqkv = (const float*)d_in[2];
    const float* Wout = (const float*)d_in[3];
    const float* bout = (const float*)d_in[4];
    float* out = (float*)d_out;

    // weight transpose + bf16 split (stateless, every call)
    convw_kernel<<<dim3(D3/32, D_/32), dim3(32, 8)>>>(Wqkv, D_, D3, 0);
    convw_kernel<<<dim3(D_/32, D_/32), dim3(32, 8)>>>(Wout, D_, D_, 1);

    // 1) QKV projection (WMMA) -> bf16 hi/lo Q,K and transposed V
    conva_kernel<<<(NTOK*D_/4 + 255)/256, 256>>>(x, NTOK*D_/4);
    mma_gemm<<<dim3(D3/128, NTOK/128), 512>>>(bqkv, nullptr, D3, D_, 1);

    // 2) tensor-core causal flash attention -> bf16 hi/lo g_Ah/g_Al
    attn_mma_kernel<<<dim3(T_/64, B_*H_), 128>>>();

    // 3) output projection (WMMA) + bias
    mma_gemm<<<dim3(D_/128, NTOK/128), 512>>>(bout, out, D_, D_, 2);
}

// round 16
// speedup vs baseline: 3.2857x; 1.6304x over previous
#include <cuda_runtime.h>
#include <cuda_bf16.h>
#include <mma.h>
#include <cstdint>

#define B_ 2
#define T_ 2048
#define D_ 1024
#define H_ 16
#define HD_ 64
#define NTOK (B_*T_)      // 4096
#define D3 (3*D_)         // 3072

using namespace nvcuda;

// ---------------------------------------------------------------------------
// Scratch (static device arrays: allocation-free).
// CRITICAL RULE (round-10 lesson): these symbols are NEVER passed as kernel
// arguments from host code. All access is from device code inside kernels.
// ---------------------------------------------------------------------------
__device__ __nv_bfloat16 g_qh[B_*H_*T_*HD_], g_ql[B_*H_*T_*HD_]; // [bh,t,hd]
__device__ __nv_bfloat16 g_kh[B_*H_*T_*HD_], g_kl[B_*H_*T_*HD_]; // [bh,t,hd]
__device__ __nv_bfloat16 g_vth[B_*H_*T_*HD_], g_vtl[B_*H_*T_*HD_]; // [bh,hd,t]

__device__ __nv_bfloat16 g_Ah[NTOK*D_];   // activation hi/lo (x, then attn out)
__device__ __nv_bfloat16 g_Al[NTOK*D_];
__device__ __nv_bfloat16 g_Wh[D3*D_];     // Wqkv^T [N=3072,K=1024] hi/lo
__device__ __nv_bfloat16 g_Wl[D3*D_];
__device__ __nv_bfloat16 g_Uh[D_*D_];     // Wout^T [N=1024,K=1024] hi/lo
__device__ __nv_bfloat16 g_Ul[D_*D_];

// ---------------------------------------------------------------------------
// warp-level bf16 MMA m16n8k16 (baseline PTX)
// ---------------------------------------------------------------------------
#define MMA16816(c, a, b)                                                     \
    asm volatile("mma.sync.aligned.m16n8k16.row.col.f32.bf16.bf16.f32 "       \
        "{%0,%1,%2,%3}, {%4,%5,%6,%7}, {%8,%9}, {%0,%1,%2,%3};"               \
        : "+f"((c)[0]), "+f"((c)[1]), "+f"((c)[2]), "+f"((c)[3])              \
        : "r"((a)[0]), "r"((a)[1]), "r"((a)[2]), "r"((a)[3]),                 \
          "r"((b)[0]), "r"((b)[1]))

__device__ __forceinline__ void split2(float a, float b,
                                       uint32_t& hi, uint32_t& lo) {
    __nv_bfloat16 ah = __float2bfloat16(a), bh = __float2bfloat16(b);
    float ar = a - __bfloat162float(ah);
    float br = b - __bfloat162float(bh);
    __nv_bfloat162 h2 = __halves2bfloat162(ah, bh);
    __nv_bfloat162 l2 = __halves2bfloat162(__float2bfloat16(ar),
                                           __float2bfloat16(br));
    hi = *(uint32_t*)&h2;
    lo = *(uint32_t*)&l2;
}

// ---------------------------------------------------------------------------
// bf16 split conversions (scratch targets resolved DEVICE-SIDE)
// ---------------------------------------------------------------------------
__global__ void conva_kernel(const float* __restrict__ A, int n4)
{
    int i = blockIdx.x * blockDim.x + threadIdx.x;
    if (i >= n4) return;
    float4 v = ((const float4*)A)[i];
    float xs[4] = {v.x, v.y, v.z, v.w};
    __nv_bfloat16 h[4], l[4];
#pragma unroll
    for (int j = 0; j < 4; j++) {
        h[j] = __float2bfloat16(xs[j]);
        l[j] = __float2bfloat16(xs[j] - __bfloat162float(h[j]));
    }
    __nv_bfloat162* Ah2 = (__nv_bfloat162*)g_Ah;
    __nv_bfloat162* Al2 = (__nv_bfloat162*)g_Al;
    Ah2[2*i+0] = __halves2bfloat162(h[0], h[1]);
    Ah2[2*i+1] = __halves2bfloat162(h[2], h[3]);
    Al2[2*i+0] = __halves2bfloat162(l[0], l[1]);
    Al2[2*i+1] = __halves2bfloat162(l[2], l[3]);
}

__global__ void convw_kernel(const float* __restrict__ W, int K, int N, int mode)
{
    __shared__ float t[32][33];
    __nv_bfloat16* __restrict__ Th = (mode == 0) ? g_Wh : g_Uh;
    __nv_bfloat16* __restrict__ Tl = (mode == 0) ? g_Wl : g_Ul;
    int n0 = blockIdx.x * 32, k0 = blockIdx.y * 32;
    int tx = threadIdx.x, ty = threadIdx.y;
#pragma unroll
    for (int i = 0; i < 4; i++)
        t[ty + i*8][tx] = W[(size_t)(k0 + ty + i*8) * N + n0 + tx];
    __syncthreads();
#pragma unroll
    for (int i = 0; i < 4; i++) {
        int n = n0 + ty + i*8, k = k0 + tx;
        float x = t[tx][ty + i*8];
        __nv_bfloat16 h = __float2bfloat16(x);
        __nv_bfloat16 l = __float2bfloat16(x - __bfloat162float(h));
        Th[(size_t)n * K + k] = h;
        Tl[(size_t)n * K + k] = l;
    }
}

// ---------------------------------------------------------------------------
// WMMA GEMM — unchanged from round-15 (protected; occupancy experiment done).
// ---------------------------------------------------------------------------
#define GKC 32
#define G_LDS 40
#define G_TILE (128*G_LDS)

__global__ void __launch_bounds__(512)
mma_gemm(const float* __restrict__ bias, float* __restrict__ C,
         int N, int K, int mode)
{
    __shared__ __nv_bfloat16 sm[4 * G_TILE];   // 40960 B
    __nv_bfloat16* sAh = sm;
    __nv_bfloat16* sAl = sm + G_TILE;
    __nv_bfloat16* sBh = sm + 2*G_TILE;
    __nv_bfloat16* sBl = sm + 3*G_TILE;

    const int tid  = threadIdx.x;
    const int wid  = tid >> 5, lane = tid & 31;
    const int wM   = wid & 3,  wN = wid >> 2;
    const int m0   = blockIdx.y * 128, n0 = blockIdx.x * 128;

    const __nv_bfloat16* __restrict__ Bh = (mode == 1) ? g_Wh : g_Uh;
    const __nv_bfloat16* __restrict__ Bl = (mode == 1) ? g_Wl : g_Ul;

    const __nv_bfloat16* pAh = g_Ah + (size_t)m0 * K;
    const __nv_bfloat16* pAl = g_Al + (size_t)m0 * K;
    const __nv_bfloat16* pBh = Bh + (size_t)n0 * K;
    const __nv_bfloat16* pBl = Bl + (size_t)n0 * K;

    wmma::fragment<wmma::accumulator, 16, 16, 16, float> acc[2][2];
#pragma unroll
    for (int mt = 0; mt < 2; mt++)
#pragma unroll
        for (int nt = 0; nt < 2; nt++) wmma::fill_fragment(acc[mt][nt], 0.0f);

    const int srow = tid >> 2, sc8 = tid & 3;
    uint4 rg[4];
    {
        size_t go = (size_t)srow * K + sc8 * 8;
        rg[0] = *(const uint4*)(pAh + go);
        rg[1] = *(const uint4*)(pAl + go);
        rg[2] = *(const uint4*)(pBh + go);
        rg[3] = *(const uint4*)(pBl + go);
    }

    const int nch = K / GKC;
    for (int ch = 0; ch < nch; ch++) {
        __syncthreads();
        {
            int so = srow * G_LDS + sc8 * 8;
            *(uint4*)(sAh + so) = rg[0];
            *(uint4*)(sAl + so) = rg[1];
            *(uint4*)(sBh + so) = rg[2];
            *(uint4*)(sBl + so) = rg[3];
        }
        __syncthreads();

        if (ch + 1 < nch) {
            size_t go = (size_t)srow * K + (ch + 1) * GKC + sc8 * 8;
            rg[0] = *(const uint4*)(pAh + go);
            rg[1] = *(const uint4*)(pAl + go);
            rg[2] = *(const uint4*)(pBh + go);
            rg[3] = *(const uint4*)(pBl + go);
        }

#pragma unroll
        for (int ks = 0; ks < 2; ks++) {
            const int k0 = ks * 16;
            wmma::fragment<wmma::matrix_a, 16, 16, 16, __nv_bfloat16,
                           wmma::row_major> ah[2], al[2];
            wmma::fragment<wmma::matrix_b, 16, 16, 16, __nv_bfloat16,
                           wmma::col_major> bh[2], bl[2];
#pragma unroll
            for (int mt = 0; mt < 2; mt++) {
                int rb = wM * 32 + mt * 16;
                wmma::load_matrix_sync(ah[mt], sAh + rb * G_LDS + k0, G_LDS);
                wmma::load_matrix_sync(al[mt], sAl + rb * G_LDS + k0, G_LDS);
            }
#pragma unroll
            for (int nt = 0; nt < 2; nt++) {
                int nb = wN * 32 + nt * 16;
                wmma::load_matrix_sync(bh[nt], sBh + nb * G_LDS + k0, G_LDS);
                wmma::load_matrix_sync(bl[nt], sBl + nb * G_LDS + k0, G_LDS);
            }
#pragma unroll
            for (int mt = 0; mt < 2; mt++)
#pragma unroll
                for (int nt = 0; nt < 2; nt++) {
                    wmma::mma_sync(acc[mt][nt], ah[mt], bh[nt], acc[mt][nt]);
                    wmma::mma_sync(acc[mt][nt], ah[mt], bl[nt], acc[mt][nt]);
                    wmma::mma_sync(acc[mt][nt], al[mt], bh[nt], acc[mt][nt]);
                }
        }
    }

    __syncthreads();
    float* scratch = (float*)sm + wid * 256;
#pragma unroll
    for (int mt = 0; mt < 2; mt++) {
#pragma unroll
        for (int nt = 0; nt < 2; nt++) {
            wmma::store_matrix_sync(scratch, acc[mt][nt], 16, wmma::mem_row_major);
            __syncwarp();
            int row0 = m0 + wM * 32 + mt * 16;
            int col0 = n0 + wN * 32 + nt * 16;
#pragma unroll
            for (int e = lane; e < 256; e += 32) {
                int rr = e >> 4, cc = e & 15;
                int r = row0 + rr, col = col0 + cc;
                float v = scratch[e] + bias[col];
                if (mode == 1) {
                    int which = col >> 10;
                    int rem   = col & 1023;
                    int h     = rem >> 6;
                    int hd    = rem & 63;
                    int b     = r / T_;
                    int t     = r - b * T_;
                    int bhh   = b * H_ + h;
                    __nv_bfloat16 vh = __float2bfloat16(v);
                    __nv_bfloat16 vl = __float2bfloat16(v - __bfloat162float(vh));
                    if (which == 0) {
                        size_t idx = ((size_t)bhh * T_ + t) * HD_ + hd;
                        g_qh[idx] = vh; g_ql[idx] = vl;
                    } else if (which == 1) {
                        size_t idx = ((size_t)bhh * T_ + t) * HD_ + hd;
                        g_kh[idx] = vh; g_kl[idx] = vl;
                    } else {
                        size_t idx = ((size_t)bhh * HD_ + hd) * T_ + t;
                        g_vth[idx] = vh; g_vtl[idx] = vl;
                    }
                } else {
                    C[(size_t)r * N + col] = v;
                }
            }
            __syncwarp();
        }
    }
}

// ---------------------------------------------------------------------------
// Tensor-core causal flash attention v2: K/V chunks staged in smem ONCE per
// CTA (4 warps shared; was 4x-redundant gmem loads), double-buffered with one
// __syncthreads per chunk; gmem prefetch overlapped with compute. Fragment
// loads are conflict-free LDS (K rows padded to 72, V rows to 40). Compute
// math byte-identical to the round-14/15 winner.
// ---------------------------------------------------------------------------
__global__ void __launch_bounds__(128)
attn_mma_kernel()
{
    __shared__ __align__(16) __nv_bfloat16 sKh[2][32][72], sKl[2][32][72];
    __shared__ __align__(16) __nv_bfloat16 sVh[2][64][40], sVl[2][64][40];

    const int tid  = threadIdx.x;
    const int wid  = tid >> 5, lane = tid & 31;
    const int grp  = lane >> 2, t2 = lane & 3;
    const int bh   = blockIdx.y;
    const int q0   = blockIdx.x * 64;
    const int qw   = q0 + wid * 16;                // warp q-row base
    const int rA   = qw + grp;                     // rows rA and rA+8
    const float scl2 = 0.125f * 1.4426950408889634f;  // scale * log2(e)

    const __nv_bfloat16* __restrict__ Qh = g_qh + (size_t)bh * (T_*HD_);
    const __nv_bfloat16* __restrict__ Ql = g_ql + (size_t)bh * (T_*HD_);
    const __nv_bfloat16* __restrict__ Kh = g_kh + (size_t)bh * (T_*HD_);
    const __nv_bfloat16* __restrict__ Kl = g_kl + (size_t)bh * (T_*HD_);
    const __nv_bfloat16* __restrict__ Vh = g_vth + (size_t)bh * (HD_*T_);
    const __nv_bfloat16* __restrict__ Vl = g_vtl + (size_t)bh * (HD_*T_);

    // Q a-fragments (4 d-steps, hi/lo), loaded once from gmem
    uint32_t qah[4][4], qal[4][4];
#pragma unroll
    for (int kd = 0; kd < 4; kd++) {
        int d = kd * 16 + t2 * 2;
        qah[kd][0] = *(const uint32_t*)&Qh[(size_t)rA * HD_ + d];
        qah[kd][1] = *(const uint32_t*)&Qh[(size_t)(rA+8) * HD_ + d];
        qah[kd][2] = *(const uint32_t*)&Qh[(size_t)rA * HD_ + d + 8];
        qah[kd][3] = *(const uint32_t*)&Qh[(size_t)(rA+8) * HD_ + d + 8];
        qal[kd][0] = *(const uint32_t*)&Ql[(size_t)rA * HD_ + d];
        qal[kd][1] = *(const uint32_t*)&Ql[(size_t)(rA+8) * HD_ + d];
        qal[kd][2] = *(const uint32_t*)&Ql[(size_t)rA * HD_ + d + 8];
        qal[kd][3] = *(const uint32_t*)&Ql[(size_t)(rA+8) * HD_ + d + 8];
    }

    float o[8][4];
#pragma unroll
    for (int dt = 0; dt < 8; dt++)
#pragma unroll
        for (int q = 0; q < 4; q++) o[dt][q] = 0.f;
    float mA = -1e30f, mB = -1e30f, lA = 0.f, lB = 0.f;

    // staging indices: K tile = 32x64 bf16 -> 256 uint4 (2/thread);
    //                  V tile = 64x32 bf16 -> 256 uint4 (2/thread)
    const int k_row0 = tid >> 3,        k_c = (tid & 7) * 8;
    const int k_row1 = (tid + 128) >> 3;
    const int v_row0 = tid >> 2,        v_c = (tid & 3) * 8;
    const int v_row1 = (tid + 128) >> 2;

    uint4 rg[8];
    {   // prefetch chunk 0
        rg[0] = *(const uint4*)&Kh[(size_t)k_row0 * HD_ + k_c];
        rg[1] = *(const uint4*)&Kh[(size_t)k_row1 * HD_ + k_c];
        rg[2] = *(const uint4*)&Kl[(size_t)k_row0 * HD_ + k_c];
        rg[3] = *(const uint4*)&Kl[(size_t)k_row1 * HD_ + k_c];
        rg[4] = *(const uint4*)&Vh[(size_t)v_row0 * T_ + v_c];
        rg[5] = *(const uint4*)&Vh[(size_t)v_row1 * T_ + v_c];
        rg[6] = *(const uint4*)&Vl[(size_t)v_row0 * T_ + v_c];
        rg[7] = *(const uint4*)&Vl[(size_t)v_row1 * T_ + v_c];
    }

    const int nch = (q0 >> 5) + 2;                 // CTA-wide chunk count
    for (int ch = 0; ch < nch; ch++) {
        const int buf = ch & 1;
        const int j0  = ch << 5;

        // store staged chunk into smem buffer
        *(uint4*)&sKh[buf][k_row0][k_c] = rg[0];
        *(uint4*)&sKh[buf][k_row1][k_c] = rg[1];
        *(uint4*)&sKl[buf][k_row0][k_c] = rg[2];
        *(uint4*)&sKl[buf][k_row1][k_c] = rg[3];
        *(uint4*)&sVh[buf][v_row0][v_c] = rg[4];
        *(uint4*)&sVh[buf][v_row1][v_c] = rg[5];
        *(uint4*)&sVl[buf][v_row0][v_c] = rg[6];
        *(uint4*)&sVl[buf][v_row1][v_c] = rg[7];
        __syncthreads();

        if (ch + 1 < nch) {                        // prefetch next chunk
            const int jn = (ch + 1) << 5;
            rg[0] = *(const uint4*)&Kh[(size_t)(jn + k_row0) * HD_ + k_c];
            rg[1] = *(const uint4*)&Kh[(size_t)(jn + k_row1) * HD_ + k_c];
            rg[2] = *(const uint4*)&Kl[(size_t)(jn + k_row0) * HD_ + k_c];
            rg[3] = *(const uint4*)&Kl[(size_t)(jn + k_row1) * HD_ + k_c];
            rg[4] = *(const uint4*)&Vh[(size_t)v_row0 * T_ + jn + v_c];
            rg[5] = *(const uint4*)&Vh[(size_t)v_row1 * T_ + jn + v_c];
            rg[6] = *(const uint4*)&Vl[(size_t)v_row0 * T_ + jn + v_c];
            rg[7] = *(const uint4*)&Vl[(size_t)v_row1 * T_ + jn + v_c];
        }

        if (j0 <= qw + 15) {                       // warp-uniform causal skip
            // ---- S = Q K^T (3-pass hi/lo), 4 n-tiles of 8 keys ----
            float s[4][4];
#pragma unroll
            for (int nt = 0; nt < 4; nt++)
#pragma unroll
                for (int q = 0; q < 4; q++) s[nt][q] = 0.f;
#pragma unroll
            for (int kd = 0; kd < 4; kd++) {
                int d = kd * 16 + t2 * 2;
#pragma unroll
                for (int nt = 0; nt < 4; nt++) {
                    int kloc = nt * 8 + grp;
                    uint32_t kb[2]  = { *(const uint32_t*)&sKh[buf][kloc][d],
                                        *(const uint32_t*)&sKh[buf][kloc][d+8] };
                    uint32_t kbl[2] = { *(const uint32_t*)&sKl[buf][kloc][d],
                                        *(const uint32_t*)&sKl[buf][kloc][d+8] };
                    MMA16816(s[nt], qah[kd], kb);
                    MMA16816(s[nt], qah[kd], kbl);
                    MMA16816(s[nt], qal[kd], kb);
                }
            }

            // ---- scale + causal mask ----
#pragma unroll
            for (int nt = 0; nt < 4; nt++) {
                int k0 = j0 + nt * 8 + t2 * 2;
                s[nt][0] = (k0     <= rA    ) ? s[nt][0] * scl2 : -1e30f;
                s[nt][1] = (k0 + 1 <= rA    ) ? s[nt][1] * scl2 : -1e30f;
                s[nt][2] = (k0     <= rA + 8) ? s[nt][2] * scl2 : -1e30f;
                s[nt][3] = (k0 + 1 <= rA + 8) ? s[nt][3] * scl2 : -1e30f;
            }

            // ---- online softmax (register-resident, quad shfl) ----
            float mxA = fmaxf(fmaxf(s[0][0], s[0][1]), fmaxf(s[1][0], s[1][1]));
            mxA = fmaxf(mxA, fmaxf(fmaxf(s[2][0], s[2][1]), fmaxf(s[3][0], s[3][1])));
            float mxB = fmaxf(fmaxf(s[0][2], s[0][3]), fmaxf(s[1][2], s[1][3]));
            mxB = fmaxf(mxB, fmaxf(fmaxf(s[2][2], s[2][3]), fmaxf(s[3][2], s[3][3])));
            mxA = fmaxf(mxA, __shfl_xor_sync(0xffffffffu, mxA, 1));
            mxA = fmaxf(mxA, __shfl_xor_sync(0xffffffffu, mxA, 2));
            mxB = fmaxf(mxB, __shfl_xor_sync(0xffffffffu, mxB, 1));
            mxB = fmaxf(mxB, __shfl_xor_sync(0xffffffffu, mxB, 2));
            float mnA = fmaxf(mA, mxA), mnB = fmaxf(mB, mxB);
            float corrA = exp2f(mA - mnA), corrB = exp2f(mB - mnB);
            mA = mnA; mB = mnB;
            lA *= corrA; lB *= corrB;
#pragma unroll
            for (int nt = 0; nt < 4; nt++) {
                s[nt][0] = exp2f(s[nt][0] - mA);
                s[nt][1] = exp2f(s[nt][1] - mA);
                s[nt][2] = exp2f(s[nt][2] - mB);
                s[nt][3] = exp2f(s[nt][3] - mB);
                lA += s[nt][0] + s[nt][1];
                lB += s[nt][2] + s[nt][3];
            }
#pragma unroll
            for (int dt = 0; dt < 8; dt++) {
                o[dt][0] *= corrA; o[dt][1] *= corrA;
                o[dt][2] *= corrB; o[dt][3] *= corrB;
            }

            // ---- repack P as bf16 hi/lo a-frags ----
            uint32_t pah[2][4], pal[2][4];
#pragma unroll
            for (int ks = 0; ks < 2; ks++) {
                split2(s[2*ks][0],   s[2*ks][1],   pah[ks][0], pal[ks][0]);
                split2(s[2*ks][2],   s[2*ks][3],   pah[ks][1], pal[ks][1]);
                split2(s[2*ks+1][0], s[2*ks+1][1], pah[ks][2], pal[ks][2]);
                split2(s[2*ks+1][2], s[2*ks+1][3], pah[ks][3], pal[ks][3]);
            }

            // ---- O += P V (3-pass hi/lo), V transposed in smem ----
#pragma unroll
            for (int ks = 0; ks < 2; ks++) {
                int kloc = ks * 16 + t2 * 2;
#pragma unroll
                for (int dt = 0; dt < 8; dt++) {
                    int dim = dt * 8 + grp;
                    uint32_t vb[2]  = { *(const uint32_t*)&sVh[buf][dim][kloc],
                                        *(const uint32_t*)&sVh[buf][dim][kloc+8] };
                    uint32_t vbl[2] = { *(const uint32_t*)&sVl[buf][dim][kloc],
                                        *(const uint32_t*)&sVl[buf][dim][kloc+8] };
                    MMA16816(o[dt], pah[ks], vb);
                    MMA16816(o[dt], pal[ks], vb);
                    MMA16816(o[dt], pah[ks], vbl);
                }
            }
        }
    }

    // finalize: reduce l over quad, normalize, write bf16 hi/lo g_Ah/g_Al
    lA += __shfl_xor_sync(0xffffffffu, lA, 1);
    lA += __shfl_xor_sync(0xffffffffu, lA, 2);
    lB += __shfl_xor_sync(0xffffffffu, lB, 1);
    lB += __shfl_xor_sync(0xffffffffu, lB, 2);
    const float invA = 1.0f / lA, invB = 1.0f / lB;
    const int b = bh >> 4, h = bh & 15;
    const size_t baseA = ((size_t)b * T_ + rA) * D_ + h * HD_;
    const size_t baseB = ((size_t)b * T_ + rA + 8) * D_ + h * HD_;
#pragma unroll
    for (int dt = 0; dt < 8; dt++) {
        int d = dt * 8 + t2 * 2;
        uint32_t hA, lAo, hB, lBo;
        split2(o[dt][0] * invA, o[dt][1] * invA, hA, lAo);
        split2(o[dt][2] * invB, o[dt][3] * invB, hB, lBo);
        *(uint32_t*)&g_Ah[baseA + d] = hA;
        *(uint32_t*)&g_Al[baseA + d] = lAo;
        *(uint32_t*)&g_Ah[baseB + d] = hB;
        *(uint32_t*)&g_Al[baseB + d] = lBo;
    }
}

// ---------------------------------------------------------------------------
// Host launcher. ONLY harness pointers cross the host/device boundary.
// ---------------------------------------------------------------------------
extern "C" void kernel_launch(void* const* d_in, const int* in_sizes, int n_in,
                              void* d_out, int out_size)
{
    const float* x    = (const float*)d_in[0];
    const float* Wqkv = (const float*)d_in[1];
    const float* bqkv = (const float*)d_in[2];
    const float* Wout = (const float*)d_in[3];
    const float* bout = (const float*)d_in[4];
    float* out = (float*)d_out;

    // weight transpose + bf16 split (stateless, every call)
    convw_kernel<<<dim3(D3/32, D_/32), dim3(32, 8)>>>(Wqkv, D_, D3, 0);
    convw_kernel<<<dim3(D_/32, D_/32), dim3(32, 8)>>>(Wout, D_, D_, 1);

    // 1) QKV projection (WMMA) -> bf16 hi/lo Q,K and transposed V
    conva_kernel<<<(NTOK*D_/4 + 255)/256, 256>>>(x, NTOK*D_/4);
    mma_gemm<<<dim3(D3/128, NTOK/128), 512>>>(bqkv, nullptr, D3, D_, 1);

    // 2) tensor-core causal flash attention -> bf16 hi/lo g_Ah/g_Al
    attn_mma_kernel<<<dim3(T_/64, B_*H_), 128>>>();

    // 3) output projection (WMMA) + bias
    mma_gemm<<<dim3(D_/128, NTOK/128), 512>>>(bout, out, D_, D_, 2);
}

// round 17
// speedup vs baseline: 3.3620x; 1.0232x over previous
#include <cuda_runtime.h>
#include <cuda_bf16.h>
#include <mma.h>
#include <cstdint>

#define B_ 2
#define T_ 2048
#define D_ 1024
#define H_ 16
#define HD_ 64
#define NTOK (B_*T_)      // 4096
#define D3 (3*D_)         // 3072

using namespace nvcuda;

// ---------------------------------------------------------------------------
// Scratch (static device arrays: allocation-free).
// CRITICAL RULE (round-10 lesson): these symbols are NEVER passed as kernel
// arguments from host code. All access is from device code inside kernels.
// ---------------------------------------------------------------------------
__device__ __nv_bfloat16 g_qh[B_*H_*T_*HD_], g_ql[B_*H_*T_*HD_]; // [bh,t,hd]
__device__ __nv_bfloat16 g_kh[B_*H_*T_*HD_], g_kl[B_*H_*T_*HD_]; // [bh,t,hd]
__device__ __nv_bfloat16 g_vth[B_*H_*T_*HD_], g_vtl[B_*H_*T_*HD_]; // [bh,hd,t]

__device__ __nv_bfloat16 g_Ah[NTOK*D_];   // activation hi/lo (x, then attn out)
__device__ __nv_bfloat16 g_Al[NTOK*D_];
__device__ __nv_bfloat16 g_Wh[D3*D_];     // Wqkv^T [N=3072,K=1024] hi/lo
__device__ __nv_bfloat16 g_Wl[D3*D_];
__device__ __nv_bfloat16 g_Uh[D_*D_];     // Wout^T [N=1024,K=1024] hi/lo
__device__ __nv_bfloat16 g_Ul[D_*D_];

// ---------------------------------------------------------------------------
// warp-level bf16 MMA m16n8k16 (baseline PTX)
// ---------------------------------------------------------------------------
#define MMA16816(c, a, b)                                                     \
    asm volatile("mma.sync.aligned.m16n8k16.row.col.f32.bf16.bf16.f32 "       \
        "{%0,%1,%2,%3}, {%4,%5,%6,%7}, {%8,%9}, {%0,%1,%2,%3};"               \
        : "+f"((c)[0]), "+f"((c)[1]), "+f"((c)[2]), "+f"((c)[3])              \
        : "r"((a)[0]), "r"((a)[1]), "r"((a)[2]), "r"((a)[3]),                 \
          "r"((b)[0]), "r"((b)[1]))

__device__ __forceinline__ void split2(float a, float b,
                                       uint32_t& hi, uint32_t& lo) {
    __nv_bfloat16 ah = __float2bfloat16(a), bh = __float2bfloat16(b);
    float ar = a - __bfloat162float(ah);
    float br = b - __bfloat162float(bh);
    __nv_bfloat162 h2 = __halves2bfloat162(ah, bh);
    __nv_bfloat162 l2 = __halves2bfloat162(__float2bfloat16(ar),
                                           __float2bfloat16(br));
    hi = *(uint32_t*)&h2;
    lo = *(uint32_t*)&l2;
}

// ---------------------------------------------------------------------------
// bf16 split conversions (scratch targets resolved DEVICE-SIDE)
// ---------------------------------------------------------------------------
__global__ void conva_kernel(const float* __restrict__ A, int n4)
{
    int i = blockIdx.x * blockDim.x + threadIdx.x;
    if (i >= n4) return;
    float4 v = ((const float4*)A)[i];
    float xs[4] = {v.x, v.y, v.z, v.w};
    __nv_bfloat16 h[4], l[4];
#pragma unroll
    for (int j = 0; j < 4; j++) {
        h[j] = __float2bfloat16(xs[j]);
        l[j] = __float2bfloat16(xs[j] - __bfloat162float(h[j]));
    }
    __nv_bfloat162* Ah2 = (__nv_bfloat162*)g_Ah;
    __nv_bfloat162* Al2 = (__nv_bfloat162*)g_Al;
    Ah2[2*i+0] = __halves2bfloat162(h[0], h[1]);
    Ah2[2*i+1] = __halves2bfloat162(h[2], h[3]);
    Al2[2*i+0] = __halves2bfloat162(l[0], l[1]);
    Al2[2*i+1] = __halves2bfloat162(l[2], l[3]);
}

__global__ void convw_kernel(const float* __restrict__ W, int K, int N, int mode)
{
    __shared__ float t[32][33];
    __nv_bfloat16* __restrict__ Th = (mode == 0) ? g_Wh : g_Uh;
    __nv_bfloat16* __restrict__ Tl = (mode == 0) ? g_Wl : g_Ul;
    int n0 = blockIdx.x * 32, k0 = blockIdx.y * 32;
    int tx = threadIdx.x, ty = threadIdx.y;
#pragma unroll
    for (int i = 0; i < 4; i++)
        t[ty + i*8][tx] = W[(size_t)(k0 + ty + i*8) * N + n0 + tx];
    __syncthreads();
#pragma unroll
    for (int i = 0; i < 4; i++) {
        int n = n0 + ty + i*8, k = k0 + tx;
        float x = t[tx][ty + i*8];
        __nv_bfloat16 h = __float2bfloat16(x);
        __nv_bfloat16 l = __float2bfloat16(x - __bfloat162float(h));
        Th[(size_t)n * K + k] = h;
        Tl[(size_t)n * K + k] = l;
    }
}

// ---------------------------------------------------------------------------
// WMMA GEMM — mainloop unchanged from round-15/16 winner. Epilogue v2:
// mode-1 stores are now u32-packed and coalesced. Q/K: 2 adjacent hd per
// store. V: scratch read transposed, 2 adjacent t per store (t is the fast
// dim of the [bh][hd][t] destination) — was 2-byte STGs at 4KB stride.
// ---------------------------------------------------------------------------
#define GKC 32
#define G_LDS 40
#define G_TILE (128*G_LDS)

__global__ void __launch_bounds__(512)
mma_gemm(const float* __restrict__ bias, float* __restrict__ C,
         int N, int K, int mode)
{
    __shared__ __nv_bfloat16 sm[4 * G_TILE];   // 40960 B
    __nv_bfloat16* sAh = sm;
    __nv_bfloat16* sAl = sm + G_TILE;
    __nv_bfloat16* sBh = sm + 2*G_TILE;
    __nv_bfloat16* sBl = sm + 3*G_TILE;

    const int tid  = threadIdx.x;
    const int wid  = tid >> 5, lane = tid & 31;
    const int wM   = wid & 3,  wN = wid >> 2;
    const int m0   = blockIdx.y * 128, n0 = blockIdx.x * 128;

    const __nv_bfloat16* __restrict__ Bh = (mode == 1) ? g_Wh : g_Uh;
    const __nv_bfloat16* __restrict__ Bl = (mode == 1) ? g_Wl : g_Ul;

    const __nv_bfloat16* pAh = g_Ah + (size_t)m0 * K;
    const __nv_bfloat16* pAl = g_Al + (size_t)m0 * K;
    const __nv_bfloat16* pBh = Bh + (size_t)n0 * K;
    const __nv_bfloat16* pBl = Bl + (size_t)n0 * K;

    wmma::fragment<wmma::accumulator, 16, 16, 16, float> acc[2][2];
#pragma unroll
    for (int mt = 0; mt < 2; mt++)
#pragma unroll
        for (int nt = 0; nt < 2; nt++) wmma::fill_fragment(acc[mt][nt], 0.0f);

    const int srow = tid >> 2, sc8 = tid & 3;
    uint4 rg[4];
    {
        size_t go = (size_t)srow * K + sc8 * 8;
        rg[0] = *(const uint4*)(pAh + go);
        rg[1] = *(const uint4*)(pAl + go);
        rg[2] = *(const uint4*)(pBh + go);
        rg[3] = *(const uint4*)(pBl + go);
    }

    const int nch = K / GKC;
    for (int ch = 0; ch < nch; ch++) {
        __syncthreads();
        {
            int so = srow * G_LDS + sc8 * 8;
            *(uint4*)(sAh + so) = rg[0];
            *(uint4*)(sAl + so) = rg[1];
            *(uint4*)(sBh + so) = rg[2];
            *(uint4*)(sBl + so) = rg[3];
        }
        __syncthreads();

        if (ch + 1 < nch) {
            size_t go = (size_t)srow * K + (ch + 1) * GKC + sc8 * 8;
            rg[0] = *(const uint4*)(pAh + go);
            rg[1] = *(const uint4*)(pAl + go);
            rg[2] = *(const uint4*)(pBh + go);
            rg[3] = *(const uint4*)(pBl + go);
        }

#pragma unroll
        for (int ks = 0; ks < 2; ks++) {
            const int k0 = ks * 16;
            wmma::fragment<wmma::matrix_a, 16, 16, 16, __nv_bfloat16,
                           wmma::row_major> ah[2], al[2];
            wmma::fragment<wmma::matrix_b, 16, 16, 16, __nv_bfloat16,
                           wmma::col_major> bh[2], bl[2];
#pragma unroll
            for (int mt = 0; mt < 2; mt++) {
                int rb = wM * 32 + mt * 16;
                wmma::load_matrix_sync(ah[mt], sAh + rb * G_LDS + k0, G_LDS);
                wmma::load_matrix_sync(al[mt], sAl + rb * G_LDS + k0, G_LDS);
            }
#pragma unroll
            for (int nt = 0; nt < 2; nt++) {
                int nb = wN * 32 + nt * 16;
                wmma::load_matrix_sync(bh[nt], sBh + nb * G_LDS + k0, G_LDS);
                wmma::load_matrix_sync(bl[nt], sBl + nb * G_LDS + k0, G_LDS);
            }
#pragma unroll
            for (int mt = 0; mt < 2; mt++)
#pragma unroll
                for (int nt = 0; nt < 2; nt++) {
                    wmma::mma_sync(acc[mt][nt], ah[mt], bh[nt], acc[mt][nt]);
                    wmma::mma_sync(acc[mt][nt], ah[mt], bl[nt], acc[mt][nt]);
                    wmma::mma_sync(acc[mt][nt], al[mt], bh[nt], acc[mt][nt]);
                }
        }
    }

    __syncthreads();
    float* scratch = (float*)sm + wid * 256;
#pragma unroll
    for (int mt = 0; mt < 2; mt++) {
#pragma unroll
        for (int nt = 0; nt < 2; nt++) {
            wmma::store_matrix_sync(scratch, acc[mt][nt], 16, wmma::mem_row_major);
            __syncwarp();
            int row0 = m0 + wM * 32 + mt * 16;
            int col0 = n0 + wN * 32 + nt * 16;
            if (mode == 1) {
                const int which = col0 >> 10;       // const per 16-col tile
                const int rem0  = col0 & 1023;
                const int h     = rem0 >> 6;
                const int hd0   = rem0 & 63;        // 16-aligned
                if (which < 2) {
                    // Q/K: [bh][t][hd]; pack 2 adjacent hd per u32 store
                    __nv_bfloat16* __restrict__ dh = (which == 0) ? g_qh : g_kh;
                    __nv_bfloat16* __restrict__ dl = (which == 0) ? g_ql : g_kl;
#pragma unroll
                    for (int e = lane; e < 128; e += 32) {
                        int rr = e >> 3, hp = (e & 7) * 2;
                        float v0 = scratch[rr * 16 + hp]     + bias[col0 + hp];
                        float v1 = scratch[rr * 16 + hp + 1] + bias[col0 + hp + 1];
                        int r = row0 + rr;
                        int b = r / T_, t = r - b * T_;
                        uint32_t hi, lo;
                        split2(v0, v1, hi, lo);
                        size_t idx = (((size_t)(b * H_ + h)) * T_ + t) * HD_
                                     + hd0 + hp;
                        *(uint32_t*)&dh[idx] = hi;
                        *(uint32_t*)&dl[idx] = lo;
                    }
                } else {
                    // V: [bh][hd][t]; transposed scratch read, pack 2 adjacent
                    // t per u32 store (t fast dim -> coalesced)
#pragma unroll
                    for (int e = lane; e < 128; e += 32) {
                        int hdi = e >> 3, tp = (e & 7) * 2;
                        float bb = bias[col0 + hdi];
                        float v0 = scratch[tp * 16 + hdi]       + bb;
                        float v1 = scratch[(tp + 1) * 16 + hdi] + bb;
                        int r = row0 + tp;            // row0 16-aligned: same b
                        int b = r / T_, t = r - b * T_;
                        uint32_t hi, lo;
                        split2(v0, v1, hi, lo);
                        size_t idx = (((size_t)(b * H_ + h)) * HD_ + hd0 + hdi)
                                     * T_ + t;
                        *(uint32_t*)&g_vth[idx] = hi;
                        *(uint32_t*)&g_vtl[idx] = lo;
                    }
                }
            } else {
#pragma unroll
                for (int e = lane; e < 256; e += 32) {
                    int rr = e >> 4, cc = e & 15;
                    int r = row0 + rr, col = col0 + cc;
                    C[(size_t)r * N + col] = scratch[e] + bias[col];
                }
            }
            __syncwarp();
        }
    }
}

// ---------------------------------------------------------------------------
// Tensor-core causal flash attention — identical to round-16 winner except
// q-tiles are scheduled HEAVY-FIRST (now tensor-bound; ragged causal waves).
// ---------------------------------------------------------------------------
__global__ void __launch_bounds__(128)
attn_mma_kernel()
{
    __shared__ __align__(16) __nv_bfloat16 sKh[2][32][72], sKl[2][32][72];
    __shared__ __align__(16) __nv_bfloat16 sVh[2][64][40], sVl[2][64][40];

    const int tid  = threadIdx.x;
    const int wid  = tid >> 5, lane = tid & 31;
    const int grp  = lane >> 2, t2 = lane & 3;
    const int bh   = blockIdx.y;
    const int q0   = (gridDim.x - 1 - blockIdx.x) * 64;   // heavy-first
    const int qw   = q0 + wid * 16;                // warp q-row base
    const int rA   = qw + grp;                     // rows rA and rA+8
    const float scl2 = 0.125f * 1.4426950408889634f;  // scale * log2(e)

    const __nv_bfloat16* __restrict__ Qh = g_qh + (size_t)bh * (T_*HD_);
    const __nv_bfloat16* __restrict__ Ql = g_ql + (size_t)bh * (T_*HD_);
    const __nv_bfloat16* __restrict__ Kh = g_kh + (size_t)bh * (T_*HD_);
    const __nv_bfloat16* __restrict__ Kl = g_kl + (size_t)bh * (T_*HD_);
    const __nv_bfloat16* __restrict__ Vh = g_vth + (size_t)bh * (HD_*T_);
    const __nv_bfloat16* __restrict__ Vl = g_vtl + (size_t)bh * (HD_*T_);

    // Q a-fragments (4 d-steps, hi/lo), loaded once from gmem
    uint32_t qah[4][4], qal[4][4];
#pragma unroll
    for (int kd = 0; kd < 4; kd++) {
        int d = kd * 16 + t2 * 2;
        qah[kd][0] = *(const uint32_t*)&Qh[(size_t)rA * HD_ + d];
        qah[kd][1] = *(const uint32_t*)&Qh[(size_t)(rA+8) * HD_ + d];
        qah[kd][2] = *(const uint32_t*)&Qh[(size_t)rA * HD_ + d + 8];
        qah[kd][3] = *(const uint32_t*)&Qh[(size_t)(rA+8) * HD_ + d + 8];
        qal[kd][0] = *(const uint32_t*)&Ql[(size_t)rA * HD_ + d];
        qal[kd][1] = *(const uint32_t*)&Ql[(size_t)(rA+8) * HD_ + d];
        qal[kd][2] = *(const uint32_t*)&Ql[(size_t)rA * HD_ + d + 8];
        qal[kd][3] = *(const uint32_t*)&Ql[(size_t)(rA+8) * HD_ + d + 8];
    }

    float o[8][4];
#pragma unroll
    for (int dt = 0; dt < 8; dt++)
#pragma unroll
        for (int q = 0; q < 4; q++) o[dt][q] = 0.f;
    float mA = -1e30f, mB = -1e30f, lA = 0.f, lB = 0.f;

    const int k_row0 = tid >> 3,        k_c = (tid & 7) * 8;
    const int k_row1 = (tid + 128) >> 3;
    const int v_row0 = tid >> 2,        v_c = (tid & 3) * 8;
    const int v_row1 = (tid + 128) >> 2;

    uint4 rg[8];
    {   // prefetch chunk 0
        rg[0] = *(const uint4*)&Kh[(size_t)k_row0 * HD_ + k_c];
        rg[1] = *(const uint4*)&Kh[(size_t)k_row1 * HD_ + k_c];
        rg[2] = *(const uint4*)&Kl[(size_t)k_row0 * HD_ + k_c];
        rg[3] = *(const uint4*)&Kl[(size_t)k_row1 * HD_ + k_c];
        rg[4] = *(const uint4*)&Vh[(size_t)v_row0 * T_ + v_c];
        rg[5] = *(const uint4*)&Vh[(size_t)v_row1 * T_ + v_c];
        rg[6] = *(const uint4*)&Vl[(size_t)v_row0 * T_ + v_c];
        rg[7] = *(const uint4*)&Vl[(size_t)v_row1 * T_ + v_c];
    }

    const int nch = (q0 >> 5) + 2;                 // CTA-wide chunk count
    for (int ch = 0; ch < nch; ch++) {
        const int buf = ch & 1;
        const int j0  = ch << 5;

        *(uint4*)&sKh[buf][k_row0][k_c] = rg[0];
        *(uint4*)&sKh[buf][k_row1][k_c] = rg[1];
        *(uint4*)&sKl[buf][k_row0][k_c] = rg[2];
        *(uint4*)&sKl[buf][k_row1][k_c] = rg[3];
        *(uint4*)&sVh[buf][v_row0][v_c] = rg[4];
        *(uint4*)&sVh[buf][v_row1][v_c] = rg[5];
        *(uint4*)&sVl[buf][v_row0][v_c] = rg[6];
        *(uint4*)&sVl[buf][v_row1][v_c] = rg[7];
        __syncthreads();

        if (ch + 1 < nch) {
            const int jn = (ch + 1) << 5;
            rg[0] = *(const uint4*)&Kh[(size_t)(jn + k_row0) * HD_ + k_c];
            rg[1] = *(const uint4*)&Kh[(size_t)(jn + k_row1) * HD_ + k_c];
            rg[2] = *(const uint4*)&Kl[(size_t)(jn + k_row0) * HD_ + k_c];
            rg[3] = *(const uint4*)&Kl[(size_t)(jn + k_row1) * HD_ + k_c];
            rg[4] = *(const uint4*)&Vh[(size_t)v_row0 * T_ + jn + v_c];
            rg[5] = *(const uint4*)&Vh[(size_t)v_row1 * T_ + jn + v_c];
            rg[6] = *(const uint4*)&Vl[(size_t)v_row0 * T_ + jn + v_c];
            rg[7] = *(const uint4*)&Vl[(size_t)v_row1 * T_ + jn + v_c];
        }

        if (j0 <= qw + 15) {                       // warp-uniform causal skip
            float s[4][4];
#pragma unroll
            for (int nt = 0; nt < 4; nt++)
#pragma unroll
                for (int q = 0; q < 4; q++) s[nt][q] = 0.f;
#pragma unroll
            for (int kd = 0; kd < 4; kd++) {
                int d = kd * 16 + t2 * 2;
#pragma unroll
                for (int nt = 0; nt < 4; nt++) {
                    int kloc = nt * 8 + grp;
                    uint32_t kb[2]  = { *(const uint32_t*)&sKh[buf][kloc][d],
                                        *(const uint32_t*)&sKh[buf][kloc][d+8] };
                    uint32_t kbl[2] = { *(const uint32_t*)&sKl[buf][kloc][d],
                                        *(const uint32_t*)&sKl[buf][kloc][d+8] };
                    MMA16816(s[nt], qah[kd], kb);
                    MMA16816(s[nt], qah[kd], kbl);
                    MMA16816(s[nt], qal[kd], kb);
                }
            }

#pragma unroll
            for (int nt = 0; nt < 4; nt++) {
                int k0 = j0 + nt * 8 + t2 * 2;
                s[nt][0] = (k0     <= rA    ) ? s[nt][0] * scl2 : -1e30f;
                s[nt][1] = (k0 + 1 <= rA    ) ? s[nt][1] * scl2 : -1e30f;
                s[nt][2] = (k0     <= rA + 8) ? s[nt][2] * scl2 : -1e30f;
                s[nt][3] = (k0 + 1 <= rA + 8) ? s[nt][3] * scl2 : -1e30f;
            }

            float mxA = fmaxf(fmaxf(s[0][0], s[0][1]), fmaxf(s[1][0], s[1][1]));
            mxA = fmaxf(mxA, fmaxf(fmaxf(s[2][0], s[2][1]), fmaxf(s[3][0], s[3][1])));
            float mxB = fmaxf(fmaxf(s[0][2], s[0][3]), fmaxf(s[1][2], s[1][3]));
            mxB = fmaxf(mxB, fmaxf(fmaxf(s[2][2], s[2][3]), fmaxf(s[3][2], s[3][3])));
            mxA = fmaxf(mxA, __shfl_xor_sync(0xffffffffu, mxA, 1));
            mxA = fmaxf(mxA, __shfl_xor_sync(0xffffffffu, mxA, 2));
            mxB = fmaxf(mxB, __shfl_xor_sync(0xffffffffu, mxB, 1));
            mxB = fmaxf(mxB, __shfl_xor_sync(0xffffffffu, mxB, 2));
            float mnA = fmaxf(mA, mxA), mnB = fmaxf(mB, mxB);
            float corrA = exp2f(mA - mnA), corrB = exp2f(mB - mnB);
            mA = mnA; mB = mnB;
            lA *= corrA; lB *= corrB;
#pragma unroll
            for (int nt = 0; nt < 4; nt++) {
                s[nt][0] = exp2f(s[nt][0] - mA);
                s[nt][1] = exp2f(s[nt][1] - mA);
                s[nt][2] = exp2f(s[nt][2] - mB);
                s[nt][3] = exp2f(s[nt][3] - mB);
                lA += s[nt][0] + s[nt][1];
                lB += s[nt][2] + s[nt][3];
            }
#pragma unroll
            for (int dt = 0; dt < 8; dt++) {
                o[dt][0] *= corrA; o[dt][1] *= corrA;
                o[dt][2] *= corrB; o[dt][3] *= corrB;
            }

            uint32_t pah[2][4], pal[2][4];
#pragma unroll
            for (int ks = 0; ks < 2; ks++) {
                split2(s[2*ks][0],   s[2*ks][1],   pah[ks][0], pal[ks][0]);
                split2(s[2*ks][2],   s[2*ks][3],   pah[ks][1], pal[ks][1]);
                split2(s[2*ks+1][0], s[2*ks+1][1], pah[ks][2], pal[ks][2]);
                split2(s[2*ks+1][2], s[2*ks+1][3], pah[ks][3], pal[ks][3]);
            }

#pragma unroll
            for (int ks = 0; ks < 2; ks++) {
                int kloc = ks * 16 + t2 * 2;
#pragma unroll
                for (int dt = 0; dt < 8; dt++) {
                    int dim = dt * 8 + grp;
                    uint32_t vb[2]  = { *(const uint32_t*)&sVh[buf][dim][kloc],
                                        *(const uint32_t*)&sVh[buf][dim][kloc+8] };
                    uint32_t vbl[2] = { *(const uint32_t*)&sVl[buf][dim][kloc],
                                        *(const uint32_t*)&sVl[buf][dim][kloc+8] };
                    MMA16816(o[dt], pah[ks], vb);
                    MMA16816(o[dt], pal[ks], vb);
                    MMA16816(o[dt], pah[ks], vbl);
                }
            }
        }
    }

    // finalize: reduce l over quad, normalize, write bf16 hi/lo g_Ah/g_Al
    lA += __shfl_xor_sync(0xffffffffu, lA, 1);
    lA += __shfl_xor_sync(0xffffffffu, lA, 2);
    lB += __shfl_xor_sync(0xffffffffu, lB, 1);
    lB += __shfl_xor_sync(0xffffffffu, lB, 2);
    const float invA = 1.0f / lA, invB = 1.0f / lB;
    const int b = bh >> 4, h = bh & 15;
    const size_t baseA = ((size_t)b * T_ + rA) * D_ + h * HD_;
    const size_t baseB = ((size_t)b * T_ + rA + 8) * D_ + h * HD_;
#pragma unroll
    for (int dt = 0; dt < 8; dt++) {
        int d = dt * 8 + t2 * 2;
        uint32_t hA, lAo, hB, lBo;
        split2(o[dt][0] * invA, o[dt][1] * invA, hA, lAo);
        split2(o[dt][2] * invB, o[dt][3] * invB, hB, lBo);
        *(uint32_t*)&g_Ah[baseA + d] = hA;
        *(uint32_t*)&g_Al[baseA + d] = lAo;
        *(uint32_t*)&g_Ah[baseB + d] = hB;
        *(uint32_t*)&g_Al[baseB + d] = lBo;
    }
}

// ---------------------------------------------------------------------------
// Host launcher. ONLY harness pointers cross the host/device boundary.
// ---------------------------------------------------------------------------
extern "C" void kernel_launch(void* const* d_in, const int* in_sizes, int n_in,
                              void* d_out, int out_size)
{
    const float* x    = (const float*)d_in[0];
    const float* Wqkv = (const float*)d_in[1];
    const float* bqkv = (const float*)d_in[2];
    const float* Wout = (const float*)d_in[3];
    const float* bout = (const float*)d_in[4];
    float* out = (float*)d_out;

    // weight transpose + bf16 split (stateless, every call)
    convw_kernel<<<dim3(D3/32, D_/32), dim3(32, 8)>>>(Wqkv, D_, D3, 0);
    convw_kernel<<<dim3(D_/32, D_/32), dim3(32, 8)>>>(Wout, D_, D_, 1);

    // 1) QKV projection (WMMA) -> bf16 hi/lo Q,K and transposed V
    conva_kernel<<<(NTOK*D_/4 + 255)/256, 256>>>(x, NTOK*D_/4);
    mma_gemm<<<dim3(D3/128, NTOK/128), 512>>>(bqkv, nullptr, D3, D_, 1);

    // 2) tensor-core causal flash attention -> bf16 hi/lo g_Ah/g_Al
    attn_mma_kernel<<<dim3(T_/64, B_*H_), 128>>>();

    // 3) output projection (WMMA) + bias
    mma_gemm<<<dim3(D_/128, NTOK/128), 512>>>(bout, out, D_, D_, 2);
}